// round 1
// baseline (speedup 1.0000x reference)
#include <cuda_runtime.h>
#include <cuda_bf16.h>

#define BATCH 4
#define SEQ 2048
#define DM 1024
#define DH 128
#define ROWS (BATCH * SEQ)   // 8192

// Scratch (allocation-free rule: __device__ globals)
__device__ float g_q[ROWS * DH];
__device__ float g_k[ROWS * DH];
__device__ float g_v[ROWS * DH];
__device__ float g_ctx[ROWS * DH];

// ---------------------------------------------------------------------------
// Kernel 1: QKV projection.  C[M=8192, N=128] = X[M, K=1024] * W[K, N]
// grid = (128, 1, 3); block = 256.  BM=64, BN=128, BK=16. Thread tile 8x4.
// ---------------------------------------------------------------------------
__global__ __launch_bounds__(256) void qkv_proj_kernel(
    const float* __restrict__ x,
    const float* __restrict__ wq,
    const float* __restrict__ wk,
    const float* __restrict__ wv)
{
    __shared__ float As[16][64];    // [k][m]
    __shared__ float Bs[16][128];   // [k][n]

    const float* w;
    float* out;
    if (blockIdx.z == 0)      { w = wq; out = g_q; }
    else if (blockIdx.z == 1) { w = wk; out = g_k; }
    else                      { w = wv; out = g_v; }

    const int tid = threadIdx.x;
    const int tx = tid & 31;        // 0..31  -> cols tx*4..tx*4+3
    const int ty = tid >> 5;        // 0..7   -> rows ty*8..ty*8+7
    const int rowBase = blockIdx.x * 64;

    float acc[8][4];
#pragma unroll
    for (int i = 0; i < 8; i++)
#pragma unroll
        for (int j = 0; j < 4; j++) acc[i][j] = 0.f;

    for (int k0 = 0; k0 < DM; k0 += 16) {
        // Load A tile: 64 rows x 16 k (1024 floats, float4 per thread)
        {
            int r = tid >> 2;             // 0..63
            int kq = (tid & 3) * 4;       // 0,4,8,12
            float4 a4 = *(const float4*)&x[(size_t)(rowBase + r) * DM + k0 + kq];
            As[kq + 0][r] = a4.x; As[kq + 1][r] = a4.y;
            As[kq + 2][r] = a4.z; As[kq + 3][r] = a4.w;
        }
        // Load B tile: 16 k x 128 n (2048 floats, 2x float4 per thread)
#pragma unroll
        for (int i = 0; i < 2; i++) {
            int f4 = tid + i * 256;       // 0..511
            int kk = f4 >> 5;             // 0..15
            int n4 = (f4 & 31) * 4;       // 0..124
            *(float4*)&Bs[kk][n4] = *(const float4*)&w[(size_t)(k0 + kk) * DH + n4];
        }
        __syncthreads();

#pragma unroll
        for (int kk = 0; kk < 16; kk++) {
            float4 a0 = *(float4*)&As[kk][ty * 8];
            float4 a1 = *(float4*)&As[kk][ty * 8 + 4];
            float4 b0 = *(float4*)&Bs[kk][tx * 4];
            float a[8] = {a0.x, a0.y, a0.z, a0.w, a1.x, a1.y, a1.z, a1.w};
            float b[4] = {b0.x, b0.y, b0.z, b0.w};
#pragma unroll
            for (int i = 0; i < 8; i++)
#pragma unroll
                for (int j = 0; j < 4; j++) acc[i][j] += a[i] * b[j];
        }
        __syncthreads();
    }

#pragma unroll
    for (int i = 0; i < 8; i++) {
        float4 o4 = make_float4(acc[i][0], acc[i][1], acc[i][2], acc[i][3]);
        *(float4*)&out[(size_t)(rowBase + ty * 8 + i) * DH + tx * 4] = o4;
    }
}

// ---------------------------------------------------------------------------
// Kernel 2: causal flash attention. One warp per query row, 8 rows per block.
// grid = (SEQ/8, BATCH); block = 256.
// ---------------------------------------------------------------------------
__global__ __launch_bounds__(256) void attn_kernel()
{
    __shared__ float qs[8][128];
    __shared__ float KsT[128][33];   // transposed K tile, padded: conflict-free
    __shared__ float Vs[32][128];

    const int b = blockIdx.y;
    const int qbase = blockIdx.x * 8;
    const int tid = threadIdx.x;
    const int lane = tid & 31;
    const int w = tid >> 5;

    const int q = qbase + w;                 // this warp's query row
    const int grow = b * SEQ + q;

    // Load this warp's q row into shared (cross-lane reads later; covered by
    // the __syncthreads inside the first tile iteration)
    *(float4*)&qs[w][lane * 4] = *(const float4*)&g_q[(size_t)grow * DH + lane * 4];

    float m = -1e30f, l = 0.f;
    float acc0 = 0.f, acc1 = 0.f, acc2 = 0.f, acc3 = 0.f;
    const float scale = 0.08838834764831845f;   // 1/sqrt(128)

    const int kend = qbase + 8;   // max kidx needed by any row in block (excl)

    for (int k0 = 0; k0 < kend; k0 += 32) {
        // Cooperative load of K (transposed) and V tiles: 32 rows x 128 each
#pragma unroll
        for (int i = 0; i < 4; i++) {
            int f4 = tid + i * 256;          // 0..1023
            int r = f4 >> 5;                 // 0..31
            int c = (f4 & 31) * 4;           // 0..124
            size_t g = (size_t)(b * SEQ + k0 + r) * DH + c;
            float4 k4 = *(const float4*)&g_k[g];
            KsT[c + 0][r] = k4.x; KsT[c + 1][r] = k4.y;
            KsT[c + 2][r] = k4.z; KsT[c + 3][r] = k4.w;
            *(float4*)&Vs[r][c] = *(const float4*)&g_v[g];
        }
        __syncthreads();

        if (k0 <= q) {   // this warp has at least one unmasked key in the tile
            int kidx = k0 + lane;
            float s = -1e30f;
            if (kidx <= q) {
                float dot = 0.f;
#pragma unroll
                for (int d = 0; d < 128; d++)
                    dot += qs[w][d] * KsT[d][lane];
                s = dot * scale;
            }
            // tile max
            float mt = s;
#pragma unroll
            for (int off = 16; off; off >>= 1)
                mt = fmaxf(mt, __shfl_xor_sync(0xffffffffu, mt, off));
            float newm = fmaxf(m, mt);
            float p = (kidx <= q) ? __expf(s - newm) : 0.f;
            float corr = __expf(m - newm);
            m = newm;
            // tile sum
            float ps = p;
#pragma unroll
            for (int off = 16; off; off >>= 1)
                ps += __shfl_xor_sync(0xffffffffu, ps, off);
            l = l * corr + ps;
            acc0 *= corr; acc1 *= corr; acc2 *= corr; acc3 *= corr;
#pragma unroll
            for (int j = 0; j < 32; j++) {
                float pj = __shfl_sync(0xffffffffu, p, j);
                float4 v4 = *(float4*)&Vs[j][lane * 4];
                acc0 += pj * v4.x; acc1 += pj * v4.y;
                acc2 += pj * v4.z; acc3 += pj * v4.w;
            }
        }
        __syncthreads();
    }

    float inv = 1.f / l;
    float4 o4 = make_float4(acc0 * inv, acc1 * inv, acc2 * inv, acc3 * inv);
    *(float4*)&g_ctx[(size_t)grow * DH + lane * 4] = o4;
}

// ---------------------------------------------------------------------------
// Kernel 3: output projection. OUT[M=8192, N=1024] = CTX[M, 128] * WO[128, N]
// grid = (16, 128); block = 256.  BM=64, BN=64, BK=32. Thread tile 4x4.
// ---------------------------------------------------------------------------
__global__ __launch_bounds__(256) void out_proj_kernel(
    const float* __restrict__ wo,
    float* __restrict__ out)
{
    __shared__ float As[32][64];    // [k][m]
    __shared__ float Bs[32][64];    // [k][n]

    const int tid = threadIdx.x;
    const int tx = tid & 15;        // cols tx*4..+3
    const int ty = tid >> 4;        // rows ty*4..+3
    const int rowBase = blockIdx.y * 64;
    const int colBase = blockIdx.x * 64;

    float acc[4][4];
#pragma unroll
    for (int i = 0; i < 4; i++)
#pragma unroll
        for (int j = 0; j < 4; j++) acc[i][j] = 0.f;

    for (int k0 = 0; k0 < DH; k0 += 32) {
        // A tile: 64 rows x 32 k = 2048 floats
#pragma unroll
        for (int i = 0; i < 2; i++) {
            int f4 = tid + i * 256;          // 0..511
            int r = f4 >> 3;                 // 0..63
            int kq = (f4 & 7) * 4;           // 0..28
            float4 a4 = *(const float4*)&g_ctx[(size_t)(rowBase + r) * DH + k0 + kq];
            As[kq + 0][r] = a4.x; As[kq + 1][r] = a4.y;
            As[kq + 2][r] = a4.z; As[kq + 3][r] = a4.w;
        }
        // B tile: 32 k x 64 n = 2048 floats
#pragma unroll
        for (int i = 0; i < 2; i++) {
            int f4 = tid + i * 256;
            int kk = f4 >> 4;                // 0..31
            int n4 = (f4 & 15) * 4;          // 0..60
            *(float4*)&Bs[kk][n4] =
                *(const float4*)&wo[(size_t)(k0 + kk) * DM + colBase + n4];
        }
        __syncthreads();

#pragma unroll
        for (int kk = 0; kk < 32; kk++) {
            float4 a4 = *(float4*)&As[kk][ty * 4];
            float4 b4 = *(float4*)&Bs[kk][tx * 4];
            float a[4] = {a4.x, a4.y, a4.z, a4.w};
            float bb[4] = {b4.x, b4.y, b4.z, b4.w};
#pragma unroll
            for (int i = 0; i < 4; i++)
#pragma unroll
                for (int j = 0; j < 4; j++) acc[i][j] += a[i] * bb[j];
        }
        __syncthreads();
    }

#pragma unroll
    for (int i = 0; i < 4; i++) {
        float4 o4 = make_float4(acc[i][0], acc[i][1], acc[i][2], acc[i][3]);
        *(float4*)&out[(size_t)(rowBase + ty * 4 + i) * DM + colBase + tx * 4] = o4;
    }
}

// ---------------------------------------------------------------------------
extern "C" void kernel_launch(void* const* d_in, const int* in_sizes, int n_in,
                              void* d_out, int out_size)
{
    (void)in_sizes; (void)n_in; (void)out_size;
    const float* x  = (const float*)d_in[0];
    const float* wq = (const float*)d_in[1];
    const float* wk = (const float*)d_in[2];
    const float* wv = (const float*)d_in[3];
    const float* wo = (const float*)d_in[4];
    float* out = (float*)d_out;

    qkv_proj_kernel<<<dim3(ROWS / 64, 1, 3), 256>>>(x, wq, wk, wv);
    attn_kernel<<<dim3(SEQ / 8, BATCH), 256>>>();
    out_proj_kernel<<<dim3(DM / 64, ROWS / 64), 256>>>(wo, out);
}

// round 2
// speedup vs baseline: 1.7934x; 1.7934x over previous
#include <cuda_runtime.h>
#include <cuda_bf16.h>

#define BATCH 4
#define SEQ 2048
#define DM 1024
#define DH 128
#define ROWS (BATCH * SEQ)   // 8192

// Scratch (allocation-free rule: __device__ globals)
__device__ float g_q[ROWS * DH];
__device__ float g_k[ROWS * DH];
__device__ float g_v[ROWS * DH];
__device__ float g_ctx[ROWS * DH];

// ---------------------------------------------------------------------------
// Kernel 1: QKV projection.  C[M=8192, N=128] = X[M, K=1024] * W[K, N]
// grid = (128, 1, 3); block = 256.  BM=64, BN=128, BK=16. Thread tile 8x4.
// ---------------------------------------------------------------------------
__global__ __launch_bounds__(256) void qkv_proj_kernel(
    const float* __restrict__ x,
    const float* __restrict__ wq,
    const float* __restrict__ wk,
    const float* __restrict__ wv)
{
    __shared__ float As[16][64];    // [k][m]
    __shared__ float Bs[16][128];   // [k][n]

    const float* w;
    float* out;
    if (blockIdx.z == 0)      { w = wq; out = g_q; }
    else if (blockIdx.z == 1) { w = wk; out = g_k; }
    else                      { w = wv; out = g_v; }

    const int tid = threadIdx.x;
    const int tx = tid & 31;
    const int ty = tid >> 5;
    const int rowBase = blockIdx.x * 64;

    float acc[8][4];
#pragma unroll
    for (int i = 0; i < 8; i++)
#pragma unroll
        for (int j = 0; j < 4; j++) acc[i][j] = 0.f;

    for (int k0 = 0; k0 < DM; k0 += 16) {
        {
            int r = tid >> 2;
            int kq = (tid & 3) * 4;
            float4 a4 = *(const float4*)&x[(size_t)(rowBase + r) * DM + k0 + kq];
            As[kq + 0][r] = a4.x; As[kq + 1][r] = a4.y;
            As[kq + 2][r] = a4.z; As[kq + 3][r] = a4.w;
        }
#pragma unroll
        for (int i = 0; i < 2; i++) {
            int f4 = tid + i * 256;
            int kk = f4 >> 5;
            int n4 = (f4 & 31) * 4;
            *(float4*)&Bs[kk][n4] = *(const float4*)&w[(size_t)(k0 + kk) * DH + n4];
        }
        __syncthreads();

#pragma unroll
        for (int kk = 0; kk < 16; kk++) {
            float4 a0 = *(float4*)&As[kk][ty * 8];
            float4 a1 = *(float4*)&As[kk][ty * 8 + 4];
            float4 b0 = *(float4*)&Bs[kk][tx * 4];
            float a[8] = {a0.x, a0.y, a0.z, a0.w, a1.x, a1.y, a1.z, a1.w};
            float b[4] = {b0.x, b0.y, b0.z, b0.w};
#pragma unroll
            for (int i = 0; i < 8; i++)
#pragma unroll
                for (int j = 0; j < 4; j++) acc[i][j] += a[i] * b[j];
        }
        __syncthreads();
    }

#pragma unroll
    for (int i = 0; i < 8; i++) {
        float4 o4 = make_float4(acc[i][0], acc[i][1], acc[i][2], acc[i][3]);
        *(float4*)&out[(size_t)(rowBase + ty * 8 + i) * DH + tx * 4] = o4;
    }
}

// ---------------------------------------------------------------------------
// Kernel 2: causal flash attention, register-tiled.
// BQ=32 queries per tile, BK=64 keys per k-tile, 256 threads (16 tx x 16 ty),
// thread tile: 2 q-rows x 4 k-cols (scores), 2 q-rows x 8 d-cols (output).
// Each block processes q-tile pair (T, 63-T) for balanced causal work.
// grid = (32, BATCH); block = 256; ~89KB dynamic smem.
// ---------------------------------------------------------------------------
#define QS_STRIDE 132
#define PS_STRIDE 68
// d-major swizzled K tile: element (d, kcol) -> word index
#define KIDX(d, c) (((d) << 6) + ((c) ^ ((((d) >> 2) & 15) << 2)))

#define SMEM_ATTN_FLOATS (32 * QS_STRIDE + 128 * 64 + 64 * 128 + 32 * PS_STRIDE)

__global__ __launch_bounds__(256, 2) void attn_kernel()
{
    extern __shared__ float sm[];
    float* Qs  = sm;                        // [32][132], pre-scaled
    float* KsT = Qs + 32 * QS_STRIDE;       // swizzled [128 d][64 kcol]
    float* Vs  = KsT + 128 * 64;            // [64][128]
    float* Ps  = Vs + 64 * 128;             // [32][68]

    const int b   = blockIdx.y;
    const int tid = threadIdx.x;
    const int tx  = tid & 15;
    const int ty  = tid >> 4;
    const int c0  = tx * 4;                 // this thread's k-col / d-col base
    const int r0  = ty * 2;
    const int r1  = r0 + 1;
    const float scale = 0.08838834764831845f;   // 1/sqrt(128)

    const size_t bbase = (size_t)b * SEQ;

    for (int half = 0; half < 2; half++) {
        const int T  = (half == 0) ? (int)blockIdx.x : 63 - (int)blockIdx.x;
        const int qb = T * 32;

        // Load Q tile (scaled): 32x128 floats, 4 float4 per thread.
#pragma unroll
        for (int i = 0; i < 4; i++) {
            int f = tid + i * 256;
            int r = f >> 5;
            int c = (f & 31) * 4;
            float4 v = *(const float4*)&g_q[(bbase + qb + r) * DH + c];
            v.x *= scale; v.y *= scale; v.z *= scale; v.w *= scale;
            *(float4*)&Qs[r * QS_STRIDE + c] = v;
        }

        float m0 = -1e30f, m1 = -1e30f, l0 = 0.f, l1 = 0.f;
        float O0[8], O1[8];
#pragma unroll
        for (int t = 0; t < 8; t++) { O0[t] = 0.f; O1[t] = 0.f; }

        const int q0i = qb + r0;
        const int q1i = qb + r1;
        const int kend = qb + 32;

        for (int k0 = 0; k0 < kend; k0 += 64) {
            __syncthreads();   // prev PV reads done (also makes Qs visible)

            // Load K (d-major swizzled) + V (row-major): 64 rows x 128 each.
#pragma unroll
            for (int i = 0; i < 8; i++) {
                int f4 = tid + i * 256;       // 0..2047
                int r  = f4 >> 5;             // key row 0..63
                int c  = (f4 & 31) * 4;       // d base
                size_t g = (bbase + k0 + r) * DH + c;
                float4 kk = *(const float4*)&g_k[g];
                KsT[KIDX(c + 0, r)] = kk.x;
                KsT[KIDX(c + 1, r)] = kk.y;
                KsT[KIDX(c + 2, r)] = kk.z;
                KsT[KIDX(c + 3, r)] = kk.w;
                *(float4*)&Vs[r * DH + c] = *(const float4*)&g_v[g];
            }
            __syncthreads();

            // ---- scores: S[2][4] over d=128 ----
            float S0[4] = {0.f, 0.f, 0.f, 0.f};
            float S1[4] = {0.f, 0.f, 0.f, 0.f};
#pragma unroll 8
            for (int d = 0; d < 128; d += 4) {
                float qa[4], qb4[4], kr[4][4];
                *(float4*)qa  = *(const float4*)&Qs[r0 * QS_STRIDE + d];
                *(float4*)qb4 = *(const float4*)&Qs[r1 * QS_STRIDE + d];
                *(float4*)kr[0] = *(const float4*)&KsT[KIDX(d + 0, c0)];
                *(float4*)kr[1] = *(const float4*)&KsT[KIDX(d + 1, c0)];
                *(float4*)kr[2] = *(const float4*)&KsT[KIDX(d + 2, c0)];
                *(float4*)kr[3] = *(const float4*)&KsT[KIDX(d + 3, c0)];
#pragma unroll
                for (int dd = 0; dd < 4; dd++)
#pragma unroll
                    for (int j = 0; j < 4; j++) {
                        S0[j] += qa[dd]  * kr[dd][j];
                        S1[j] += qb4[dd] * kr[dd][j];
                    }
            }

            // causal mask (only partial tiles)
            if (k0 + 63 > qb) {
#pragma unroll
                for (int j = 0; j < 4; j++) {
                    int kidx = k0 + c0 + j;
                    if (kidx > q0i) S0[j] = -1e30f;
                    if (kidx > q1i) S1[j] = -1e30f;
                }
            }

            // ---- online softmax (row groups = 16 contiguous lanes) ----
            float mt0 = fmaxf(fmaxf(S0[0], S0[1]), fmaxf(S0[2], S0[3]));
            float mt1 = fmaxf(fmaxf(S1[0], S1[1]), fmaxf(S1[2], S1[3]));
#pragma unroll
            for (int off = 8; off; off >>= 1) {
                mt0 = fmaxf(mt0, __shfl_xor_sync(0xffffffffu, mt0, off));
                mt1 = fmaxf(mt1, __shfl_xor_sync(0xffffffffu, mt1, off));
            }
            float nm0 = fmaxf(m0, mt0), nm1 = fmaxf(m1, mt1);
            float corr0 = __expf(m0 - nm0), corr1 = __expf(m1 - nm1);
            m0 = nm0; m1 = nm1;

            float p0[4], p1[4];
#pragma unroll
            for (int j = 0; j < 4; j++) {
                p0[j] = __expf(S0[j] - nm0);
                p1[j] = __expf(S1[j] - nm1);
            }
            float rs0 = (p0[0] + p0[1]) + (p0[2] + p0[3]);
            float rs1 = (p1[0] + p1[1]) + (p1[2] + p1[3]);
#pragma unroll
            for (int off = 8; off; off >>= 1) {
                rs0 += __shfl_xor_sync(0xffffffffu, rs0, off);
                rs1 += __shfl_xor_sync(0xffffffffu, rs1, off);
            }
            l0 = l0 * corr0 + rs0;
            l1 = l1 * corr1 + rs1;
#pragma unroll
            for (int t = 0; t < 8; t++) { O0[t] *= corr0; O1[t] *= corr1; }

            *(float4*)&Ps[r0 * PS_STRIDE + c0] = *(float4*)p0;
            *(float4*)&Ps[r1 * PS_STRIDE + c0] = *(float4*)p1;
            __syncthreads();

            // ---- PV: O[2 rows][8 d-cols], d-cols = c0..c0+3 and 64+c0..+3 ----
#pragma unroll 4
            for (int j = 0; j < 64; j++) {
                float pa = Ps[r0 * PS_STRIDE + j];
                float pb = Ps[r1 * PS_STRIDE + j];
                float va[4], vb[4];
                *(float4*)va = *(const float4*)&Vs[j * DH + c0];
                *(float4*)vb = *(const float4*)&Vs[j * DH + 64 + c0];
#pragma unroll
                for (int t = 0; t < 4; t++) {
                    O0[t]     += pa * va[t];
                    O0[t + 4] += pa * vb[t];
                    O1[t]     += pb * va[t];
                    O1[t + 4] += pb * vb[t];
                }
            }
        }

        // ---- write output rows ----
        float inv0 = 1.f / l0, inv1 = 1.f / l1;
        float4 o;
        o = make_float4(O0[0] * inv0, O0[1] * inv0, O0[2] * inv0, O0[3] * inv0);
        *(float4*)&g_ctx[(bbase + q0i) * DH + c0] = o;
        o = make_float4(O0[4] * inv0, O0[5] * inv0, O0[6] * inv0, O0[7] * inv0);
        *(float4*)&g_ctx[(bbase + q0i) * DH + 64 + c0] = o;
        o = make_float4(O1[0] * inv1, O1[1] * inv1, O1[2] * inv1, O1[3] * inv1);
        *(float4*)&g_ctx[(bbase + q1i) * DH + c0] = o;
        o = make_float4(O1[4] * inv1, O1[5] * inv1, O1[6] * inv1, O1[7] * inv1);
        *(float4*)&g_ctx[(bbase + q1i) * DH + 64 + c0] = o;

        __syncthreads();   // Qs reload next half vs this half's stragglers
    }
}

// ---------------------------------------------------------------------------
// Kernel 3: output projection. OUT[M=8192, N=1024] = CTX[M, 128] * WO[128, N]
// grid = (16, 128); block = 256.  BM=64, BN=64, BK=32. Thread tile 4x4.
// ---------------------------------------------------------------------------
__global__ __launch_bounds__(256) void out_proj_kernel(
    const float* __restrict__ wo,
    float* __restrict__ out)
{
    __shared__ float As[32][64];
    __shared__ float Bs[32][64];

    const int tid = threadIdx.x;
    const int tx = tid & 15;
    const int ty = tid >> 4;
    const int rowBase = blockIdx.y * 64;
    const int colBase = blockIdx.x * 64;

    float acc[4][4];
#pragma unroll
    for (int i = 0; i < 4; i++)
#pragma unroll
        for (int j = 0; j < 4; j++) acc[i][j] = 0.f;

    for (int k0 = 0; k0 < DH; k0 += 32) {
#pragma unroll
        for (int i = 0; i < 2; i++) {
            int f4 = tid + i * 256;
            int r = f4 >> 3;
            int kq = (f4 & 7) * 4;
            float4 a4 = *(const float4*)&g_ctx[(size_t)(rowBase + r) * DH + k0 + kq];
            As[kq + 0][r] = a4.x; As[kq + 1][r] = a4.y;
            As[kq + 2][r] = a4.z; As[kq + 3][r] = a4.w;
        }
#pragma unroll
        for (int i = 0; i < 2; i++) {
            int f4 = tid + i * 256;
            int kk = f4 >> 4;
            int n4 = (f4 & 15) * 4;
            *(float4*)&Bs[kk][n4] =
                *(const float4*)&wo[(size_t)(k0 + kk) * DM + colBase + n4];
        }
        __syncthreads();

#pragma unroll
        for (int kk = 0; kk < 32; kk++) {
            float4 a4 = *(float4*)&As[kk][ty * 4];
            float4 b4 = *(float4*)&Bs[kk][tx * 4];
            float a[4] = {a4.x, a4.y, a4.z, a4.w};
            float bb[4] = {b4.x, b4.y, b4.z, b4.w};
#pragma unroll
            for (int i = 0; i < 4; i++)
#pragma unroll
                for (int j = 0; j < 4; j++) acc[i][j] += a[i] * bb[j];
        }
        __syncthreads();
    }

#pragma unroll
    for (int i = 0; i < 4; i++) {
        float4 o4 = make_float4(acc[i][0], acc[i][1], acc[i][2], acc[i][3]);
        *(float4*)&out[(size_t)(rowBase + ty * 4 + i) * DM + colBase + tx * 4] = o4;
    }
}

// ---------------------------------------------------------------------------
extern "C" void kernel_launch(void* const* d_in, const int* in_sizes, int n_in,
                              void* d_out, int out_size)
{
    (void)in_sizes; (void)n_in; (void)out_size;
    const float* x  = (const float*)d_in[0];
    const float* wq = (const float*)d_in[1];
    const float* wk = (const float*)d_in[2];
    const float* wv = (const float*)d_in[3];
    const float* wo = (const float*)d_in[4];
    float* out = (float*)d_out;

    const int attn_smem = SMEM_ATTN_FLOATS * 4;   // ~91KB
    cudaFuncSetAttribute(attn_kernel,
                         cudaFuncAttributeMaxDynamicSharedMemorySize, attn_smem);

    qkv_proj_kernel<<<dim3(ROWS / 64, 1, 3), 256>>>(x, wq, wk, wv);
    attn_kernel<<<dim3(32, BATCH), 256, attn_smem>>>();
    out_proj_kernel<<<dim3(DM / 64, ROWS / 64), 256>>>(wo, out);
}

// round 8
// speedup vs baseline: 2.1888x; 1.2205x over previous
#include <cuda_runtime.h>
#include <cuda_bf16.h>
#include <cstdint>

#define BATCH 4
#define SEQ 2048
#define DM 1024
#define DH 128
#define ROWS (BATCH * SEQ)   // 8192

// ---------------------------------------------------------------------------
// Scratch (__device__ globals per allocation rules)
// ---------------------------------------------------------------------------
__device__ __align__(16) float g_q[ROWS * DH];
__device__ __align__(16) float g_k[ROWS * DH];
__device__ __align__(16) float g_v[ROWS * DH];
__device__ __align__(16) float g_ctx[ROWS * DH];
// transposed bf16 hi/lo weights: wT[z][n][k] = w_z[k][n]
__device__ __align__(16) __nv_bfloat16 g_wThi[3 * DH * DM];
__device__ __align__(16) __nv_bfloat16 g_wTlo[3 * DH * DM];
__device__ __align__(16) __nv_bfloat16 g_woThi[DM * DH];
__device__ __align__(16) __nv_bfloat16 g_woTlo[DM * DH];

// ---------------------------------------------------------------------------
// helpers
// ---------------------------------------------------------------------------
__device__ __forceinline__ uint32_t pack_bf16x2(float x, float y) {
    __nv_bfloat162 t(__float2bfloat16(x), __float2bfloat16(y));  // x -> low
    return *(uint32_t*)&t;
}
__device__ __forceinline__ void split_bf16(float v, __nv_bfloat16& h, float& lo) {
    h = __float2bfloat16(v);
    lo = v - __bfloat162float(h);
}

// mma.sync m16n8k16 bf16 -> f32 (target-portable PTX, runs on HMMA pipe)
#define MMA4(c, a, b) asm volatile( \
    "mma.sync.aligned.m16n8k16.row.col.f32.bf16.bf16.f32 " \
    "{%0,%1,%2,%3}, {%4,%5,%6,%7}, {%8,%9}, {%0,%1,%2,%3};" \
    : "+f"((c)[0]), "+f"((c)[1]), "+f"((c)[2]), "+f"((c)[3]) \
    : "r"((a)[0]), "r"((a)[1]), "r"((a)[2]), "r"((a)[3]), \
      "r"((b)[0]), "r"((b)[1]))

// ---------------------------------------------------------------------------
// Weight transpose+split preps (tiny)
// ---------------------------------------------------------------------------
__global__ void prep_w_qkv(const float* __restrict__ wq,
                           const float* __restrict__ wk,
                           const float* __restrict__ wv) {
    int k = blockIdx.x, z = blockIdx.y, n = threadIdx.x;   // 128 thr
    const float* w = (z == 0) ? wq : (z == 1) ? wk : wv;
    float v = w[k * DH + n];
    __nv_bfloat16 h; float lo; split_bf16(v, h, lo);
    size_t o = (size_t)z * DH * DM + (size_t)n * DM + k;
    g_wThi[o] = h; g_wTlo[o] = __float2bfloat16(lo);
}
__global__ void prep_wo(const float* __restrict__ wo) {
    int k = blockIdx.x;                                    // 128 blocks, 256 thr
#pragma unroll
    for (int i = 0; i < 4; i++) {
        int n = threadIdx.x + i * 256;
        float v = wo[(size_t)k * DM + n];
        __nv_bfloat16 h; float lo; split_bf16(v, h, lo);
        g_woThi[(size_t)n * DH + k] = h;
        g_woTlo[(size_t)n * DH + k] = __float2bfloat16(lo);
    }
}

// ---------------------------------------------------------------------------
// Generic warp-mma GEMM body.
// C[64, 128] = A[64, K](f32, split hi/lo on the fly) x B[n][k](bf16 hi/lo)
// BK=32 chunks, double-buffered smem + register prefetch.
// 8 warps as 2(m) x 4(n); warp tile 32x32; m16n8k16 fragments.
// smem halves-stride 40 -> conflict-free fragment LDS.
// ---------------------------------------------------------------------------
#define SA 40
#define SB 40
#define ABYTES (64 * SA * 2)                 // 5120
#define BBYTES (128 * SB * 2)                // 10240
#define BUFB (2 * ABYTES + 2 * BBYTES)       // 30720
#define GEMM_SMEM (2 * BUFB)                 // 61440

__device__ __forceinline__ void gemm_body(
    const float* __restrict__ A, int lda,
    const __nv_bfloat16* __restrict__ Bhig,
    const __nv_bfloat16* __restrict__ Blog, int ldb,
    float* __restrict__ C, int ldc, int nc)
{
    extern __shared__ char smg[];
    const int tid  = threadIdx.x;
    const int lane = tid & 31;
    const int wid  = tid >> 5;
    const int warpM = wid >> 2;      // 0..1
    const int warpN = wid & 3;       // 0..3
    const int qr = lane >> 2, qc = lane & 3;

    float acc[2][4][4];
#pragma unroll
    for (int mt = 0; mt < 2; mt++)
#pragma unroll
        for (int nt = 0; nt < 4; nt++)
#pragma unroll
            for (int i = 0; i < 4; i++) acc[mt][nt][i] = 0.f;

    float4 apre[2];
    uint4  bpre[4];

    // prefetch chunk 0
    {
        const int k0 = 0;
#pragma unroll
        for (int i = 0; i < 2; i++) {
            int idx = tid + i * 256, r = idx >> 3, c4 = idx & 7;
            apre[i] = *(const float4*)(A + (size_t)r * lda + k0 + c4 * 4);
        }
        int r = tid >> 1, g = tid & 1;
        const __nv_bfloat16* s = Bhig + (size_t)r * ldb + k0 + g * 16;
        bpre[0] = ((const uint4*)s)[0]; bpre[1] = ((const uint4*)s)[1];
        s = Blog + (size_t)r * ldb + k0 + g * 16;
        bpre[2] = ((const uint4*)s)[0]; bpre[3] = ((const uint4*)s)[1];
    }

    for (int c = 0; c < nc; c++) {
        const int p = c & 1;
        char* buf = smg + p * BUFB;

        // ---- STS prefetched chunk c ----
#pragma unroll
        for (int i = 0; i < 2; i++) {
            int idx = tid + i * 256, r = idx >> 3, c4 = idx & 7;
            float4 v = apre[i];
            __nv_bfloat16 h0, h1, h2, h3; float l0, l1, l2, l3;
            split_bf16(v.x, h0, l0); split_bf16(v.y, h1, l1);
            split_bf16(v.z, h2, l2); split_bf16(v.w, h3, l3);
            __nv_bfloat162 ha(h0, h1), hb(h2, h3);
            uint2 hv = make_uint2(*(uint32_t*)&ha, *(uint32_t*)&hb);
            uint2 lv = make_uint2(pack_bf16x2(l0, l1), pack_bf16x2(l2, l3));
            *(uint2*)(buf + r * (SA * 2) + c4 * 8) = hv;
            *(uint2*)(buf + ABYTES + r * (SA * 2) + c4 * 8) = lv;
        }
        {
            int r = tid >> 1, g = tid & 1;
            char* d = buf + 2 * ABYTES + r * (SB * 2) + g * 32;
            *(uint4*)(d) = bpre[0];
            *(uint4*)(d + 16) = bpre[1];
            *(uint4*)(d + BBYTES) = bpre[2];
            *(uint4*)(d + BBYTES + 16) = bpre[3];
        }
        __syncthreads();

        // ---- prefetch chunk c+1 ----
        if (c + 1 < nc) {
            const int k0 = (c + 1) * 32;
#pragma unroll
            for (int i = 0; i < 2; i++) {
                int idx = tid + i * 256, r = idx >> 3, c4 = idx & 7;
                apre[i] = *(const float4*)(A + (size_t)r * lda + k0 + c4 * 4);
            }
            int r = tid >> 1, g = tid & 1;
            const __nv_bfloat16* s = Bhig + (size_t)r * ldb + k0 + g * 16;
            bpre[0] = ((const uint4*)s)[0]; bpre[1] = ((const uint4*)s)[1];
            s = Blog + (size_t)r * ldb + k0 + g * 16;
            bpre[2] = ((const uint4*)s)[0]; bpre[3] = ((const uint4*)s)[1];
        }

        // ---- MMA on chunk c ----
        const char* Ah = buf;
        const char* Al = buf + ABYTES;
        const char* Bh = buf + 2 * ABYTES;
        const char* Bl = buf + 2 * ABYTES + BBYTES;
#pragma unroll
        for (int s = 0; s < 2; s++) {
            const int kb = s * 16 + qc * 2;
            uint32_t ah[2][4], al[2][4], bh[4][2], bl[4][2];
#pragma unroll
            for (int mt = 0; mt < 2; mt++) {
                int r = warpM * 32 + mt * 16 + qr;
                ah[mt][0] = *(const uint32_t*)(Ah + (r * SA + kb) * 2);
                ah[mt][1] = *(const uint32_t*)(Ah + ((r + 8) * SA + kb) * 2);
                ah[mt][2] = *(const uint32_t*)(Ah + (r * SA + kb + 8) * 2);
                ah[mt][3] = *(const uint32_t*)(Ah + ((r + 8) * SA + kb + 8) * 2);
                al[mt][0] = *(const uint32_t*)(Al + (r * SA + kb) * 2);
                al[mt][1] = *(const uint32_t*)(Al + ((r + 8) * SA + kb) * 2);
                al[mt][2] = *(const uint32_t*)(Al + (r * SA + kb + 8) * 2);
                al[mt][3] = *(const uint32_t*)(Al + ((r + 8) * SA + kb + 8) * 2);
            }
#pragma unroll
            for (int nt = 0; nt < 4; nt++) {
                int n = warpN * 32 + nt * 8 + qr;
                bh[nt][0] = *(const uint32_t*)(Bh + (n * SB + kb) * 2);
                bh[nt][1] = *(const uint32_t*)(Bh + (n * SB + kb + 8) * 2);
                bl[nt][0] = *(const uint32_t*)(Bl + (n * SB + kb) * 2);
                bl[nt][1] = *(const uint32_t*)(Bl + (n * SB + kb + 8) * 2);
            }
#pragma unroll
            for (int mt = 0; mt < 2; mt++)
#pragma unroll
                for (int nt = 0; nt < 4; nt++) {
                    MMA4(acc[mt][nt], ah[mt], bh[nt]);
                    MMA4(acc[mt][nt], ah[mt], bl[nt]);
                    MMA4(acc[mt][nt], al[mt], bh[nt]);
                }
        }
        __syncthreads();
    }

    // ---- epilogue: fragment -> f32 STG ----
#pragma unroll
    for (int mt = 0; mt < 2; mt++)
#pragma unroll
        for (int nt = 0; nt < 4; nt++) {
            int r = warpM * 32 + mt * 16 + qr;
            int col = warpN * 32 + nt * 8 + qc * 2;
            float2 v0 = make_float2(acc[mt][nt][0], acc[mt][nt][1]);
            float2 v1 = make_float2(acc[mt][nt][2], acc[mt][nt][3]);
            *(float2*)(C + (size_t)r * ldc + col) = v0;
            *(float2*)(C + (size_t)(r + 8) * ldc + col) = v1;
        }
}

// qkv: grid (128, 3): 64 rows per CTA, K=1024 (nc=32), N=128.
__global__ __launch_bounds__(256, 2) void qkv_mma_kernel(const float* __restrict__ x) {
    const int z = blockIdx.y, bx = blockIdx.x;
    const __nv_bfloat16* Bh = g_wThi + (size_t)z * DH * DM;
    const __nv_bfloat16* Bl = g_wTlo + (size_t)z * DH * DM;
    float* C = ((z == 0) ? g_q : (z == 1) ? g_k : g_v) + (size_t)bx * 64 * DH;
    gemm_body(x + (size_t)bx * 64 * DM, DM, Bh, Bl, DM, C, DH, 32);
}

// out: grid (128, 8): 64 rows, n-slab 128, K=128 (nc=4).
__global__ __launch_bounds__(256, 2) void out_mma_kernel(float* __restrict__ out) {
    const int bx = blockIdx.x, by = blockIdx.y;
    const __nv_bfloat16* Bh = g_woThi + (size_t)by * 128 * DH;
    const __nv_bfloat16* Bl = g_woTlo + (size_t)by * 128 * DH;
    float* C = out + (size_t)bx * 64 * DM + by * 128;
    gemm_body(g_ctx + (size_t)bx * 64 * DH, DH, Bh, Bl, DH, C, DM, 4);
}

// ---------------------------------------------------------------------------
// Causal flash attention (unchanged; register-tiled SIMT, passing at R2)
// ---------------------------------------------------------------------------
#define QS_STRIDE 132
#define PS_STRIDE 68
#define KIDX(d, c) (((d) << 6) + ((c) ^ ((((d) >> 2) & 15) << 2)))
#define SMEM_ATTN_FLOATS (32 * QS_STRIDE + 128 * 64 + 64 * 128 + 32 * PS_STRIDE)

__global__ __launch_bounds__(256, 2) void attn_kernel()
{
    extern __shared__ float sm[];
    float* Qs  = sm;
    float* KsT = Qs + 32 * QS_STRIDE;
    float* Vs  = KsT + 128 * 64;
    float* Ps  = Vs + 64 * 128;

    const int b   = blockIdx.y;
    const int tid = threadIdx.x;
    const int tx  = tid & 15;
    const int ty  = tid >> 4;
    const int c0  = tx * 4;
    const int r0  = ty * 2;
    const int r1  = r0 + 1;
    const float scale = 0.08838834764831845f;

    const size_t bbase = (size_t)b * SEQ;

    for (int half = 0; half < 2; half++) {
        const int T  = (half == 0) ? (int)blockIdx.x : 63 - (int)blockIdx.x;
        const int qb = T * 32;

#pragma unroll
        for (int i = 0; i < 4; i++) {
            int f = tid + i * 256;
            int r = f >> 5;
            int c = (f & 31) * 4;
            float4 v = *(const float4*)&g_q[(bbase + qb + r) * DH + c];
            v.x *= scale; v.y *= scale; v.z *= scale; v.w *= scale;
            *(float4*)&Qs[r * QS_STRIDE + c] = v;
        }

        float m0 = -1e30f, m1 = -1e30f, l0 = 0.f, l1 = 0.f;
        float O0[8], O1[8];
#pragma unroll
        for (int t = 0; t < 8; t++) { O0[t] = 0.f; O1[t] = 0.f; }

        const int q0i = qb + r0;
        const int q1i = qb + r1;
        const int kend = qb + 32;

        for (int k0 = 0; k0 < kend; k0 += 64) {
            __syncthreads();
#pragma unroll
            for (int i = 0; i < 8; i++) {
                int f4 = tid + i * 256;
                int r  = f4 >> 5;
                int c  = (f4 & 31) * 4;
                size_t g = (bbase + k0 + r) * DH + c;
                float4 kk = *(const float4*)&g_k[g];
                KsT[KIDX(c + 0, r)] = kk.x;
                KsT[KIDX(c + 1, r)] = kk.y;
                KsT[KIDX(c + 2, r)] = kk.z;
                KsT[KIDX(c + 3, r)] = kk.w;
                *(float4*)&Vs[r * DH + c] = *(const float4*)&g_v[g];
            }
            __syncthreads();

            float S0[4] = {0.f, 0.f, 0.f, 0.f};
            float S1[4] = {0.f, 0.f, 0.f, 0.f};
#pragma unroll 8
            for (int d = 0; d < 128; d += 4) {
                float qa[4], qb4[4], kr[4][4];
                *(float4*)qa  = *(const float4*)&Qs[r0 * QS_STRIDE + d];
                *(float4*)qb4 = *(const float4*)&Qs[r1 * QS_STRIDE + d];
                *(float4*)kr[0] = *(const float4*)&KsT[KIDX(d + 0, c0)];
                *(float4*)kr[1] = *(const float4*)&KsT[KIDX(d + 1, c0)];
                *(float4*)kr[2] = *(const float4*)&KsT[KIDX(d + 2, c0)];
                *(float4*)kr[3] = *(const float4*)&KsT[KIDX(d + 3, c0)];
#pragma unroll
                for (int dd = 0; dd < 4; dd++)
#pragma unroll
                    for (int j = 0; j < 4; j++) {
                        S0[j] += qa[dd]  * kr[dd][j];
                        S1[j] += qb4[dd] * kr[dd][j];
                    }
            }

            if (k0 + 63 > qb) {
#pragma unroll
                for (int j = 0; j < 4; j++) {
                    int kidx = k0 + c0 + j;
                    if (kidx > q0i) S0[j] = -1e30f;
                    if (kidx > q1i) S1[j] = -1e30f;
                }
            }

            float mt0 = fmaxf(fmaxf(S0[0], S0[1]), fmaxf(S0[2], S0[3]));
            float mt1 = fmaxf(fmaxf(S1[0], S1[1]), fmaxf(S1[2], S1[3]));
#pragma unroll
            for (int off = 8; off; off >>= 1) {
                mt0 = fmaxf(mt0, __shfl_xor_sync(0xffffffffu, mt0, off));
                mt1 = fmaxf(mt1, __shfl_xor_sync(0xffffffffu, mt1, off));
            }
            float nm0 = fmaxf(m0, mt0), nm1 = fmaxf(m1, mt1);
            float corr0 = __expf(m0 - nm0), corr1 = __expf(m1 - nm1);
            m0 = nm0; m1 = nm1;

            float p0[4], p1[4];
#pragma unroll
            for (int j = 0; j < 4; j++) {
                p0[j] = __expf(S0[j] - nm0);
                p1[j] = __expf(S1[j] - nm1);
            }
            float rs0 = (p0[0] + p0[1]) + (p0[2] + p0[3]);
            float rs1 = (p1[0] + p1[1]) + (p1[2] + p1[3]);
#pragma unroll
            for (int off = 8; off; off >>= 1) {
                rs0 += __shfl_xor_sync(0xffffffffu, rs0, off);
                rs1 += __shfl_xor_sync(0xffffffffu, rs1, off);
            }
            l0 = l0 * corr0 + rs0;
            l1 = l1 * corr1 + rs1;
#pragma unroll
            for (int t = 0; t < 8; t++) { O0[t] *= corr0; O1[t] *= corr1; }

            *(float4*)&Ps[r0 * PS_STRIDE + c0] = *(float4*)p0;
            *(float4*)&Ps[r1 * PS_STRIDE + c0] = *(float4*)p1;
            __syncthreads();

#pragma unroll 4
            for (int j = 0; j < 64; j++) {
                float pa = Ps[r0 * PS_STRIDE + j];
                float pb = Ps[r1 * PS_STRIDE + j];
                float va[4], vb[4];
                *(float4*)va = *(const float4*)&Vs[j * DH + c0];
                *(float4*)vb = *(const float4*)&Vs[j * DH + 64 + c0];
#pragma unroll
                for (int t = 0; t < 4; t++) {
                    O0[t]     += pa * va[t];
                    O0[t + 4] += pa * vb[t];
                    O1[t]     += pb * va[t];
                    O1[t + 4] += pb * vb[t];
                }
            }
        }

        float inv0 = 1.f / l0, inv1 = 1.f / l1;
        float4 o;
        o = make_float4(O0[0] * inv0, O0[1] * inv0, O0[2] * inv0, O0[3] * inv0);
        *(float4*)&g_ctx[(bbase + q0i) * DH + c0] = o;
        o = make_float4(O0[4] * inv0, O0[5] * inv0, O0[6] * inv0, O0[7] * inv0);
        *(float4*)&g_ctx[(bbase + q0i) * DH + 64 + c0] = o;
        o = make_float4(O1[0] * inv1, O1[1] * inv1, O1[2] * inv1, O1[3] * inv1);
        *(float4*)&g_ctx[(bbase + q1i) * DH + c0] = o;
        o = make_float4(O1[4] * inv1, O1[5] * inv1, O1[6] * inv1, O1[7] * inv1);
        *(float4*)&g_ctx[(bbase + q1i) * DH + 64 + c0] = o;

        __syncthreads();
    }
}

// ---------------------------------------------------------------------------
extern "C" void kernel_launch(void* const* d_in, const int* in_sizes, int n_in,
                              void* d_out, int out_size)
{
    (void)in_sizes; (void)n_in; (void)out_size;
    const float* x  = (const float*)d_in[0];
    const float* wq = (const float*)d_in[1];
    const float* wk = (const float*)d_in[2];
    const float* wv = (const float*)d_in[3];
    const float* wo = (const float*)d_in[4];
    float* out = (float*)d_out;

    const int attn_smem = SMEM_ATTN_FLOATS * 4;   // ~91KB
    cudaFuncSetAttribute(attn_kernel,
                         cudaFuncAttributeMaxDynamicSharedMemorySize, attn_smem);
    cudaFuncSetAttribute(qkv_mma_kernel,
                         cudaFuncAttributeMaxDynamicSharedMemorySize, GEMM_SMEM);
    cudaFuncSetAttribute(out_mma_kernel,
                         cudaFuncAttributeMaxDynamicSharedMemorySize, GEMM_SMEM);

    prep_w_qkv<<<dim3(DM, 3), DH>>>(wq, wk, wv);
    prep_wo<<<DH, 256>>>(wo);
    qkv_mma_kernel<<<dim3(ROWS / 64, 3), 256, GEMM_SMEM>>>(x);
    attn_kernel<<<dim3(32, BATCH), 256, attn_smem>>>();
    out_mma_kernel<<<dim3(ROWS / 64, DM / 128), 256, GEMM_SMEM>>>(out);
}

// round 10
// speedup vs baseline: 3.4030x; 1.5547x over previous
#include <cuda_runtime.h>
#include <cuda_bf16.h>
#include <cstdint>

#define BATCH 4
#define SEQ 2048
#define DM 1024
#define DH 128
#define ROWS (BATCH * SEQ)   // 8192

// ---------------------------------------------------------------------------
// Scratch (__device__ globals per allocation rules)
// ---------------------------------------------------------------------------
__device__ __align__(16) float g_v[ROWS * DH];      // V f32 (feeds transpose)
__device__ __align__(16) float g_ctx[ROWS * DH];
// bf16 hi/lo activations
__device__ __align__(16) __nv_bfloat16 g_qhi[ROWS * DH];
__device__ __align__(16) __nv_bfloat16 g_qlo[ROWS * DH];
__device__ __align__(16) __nv_bfloat16 g_khi[ROWS * DH];
__device__ __align__(16) __nv_bfloat16 g_klo[ROWS * DH];
__device__ __align__(16) __nv_bfloat16 g_vthi[BATCH * DH * SEQ];  // [b][d][key]
__device__ __align__(16) __nv_bfloat16 g_vtlo[BATCH * DH * SEQ];
// transposed bf16 hi/lo weights: wT[z][n][k] = w_z[k][n]
__device__ __align__(16) __nv_bfloat16 g_wThi[3 * DH * DM];
__device__ __align__(16) __nv_bfloat16 g_wTlo[3 * DH * DM];
__device__ __align__(16) __nv_bfloat16 g_woThi[DM * DH];
__device__ __align__(16) __nv_bfloat16 g_woTlo[DM * DH];

// ---------------------------------------------------------------------------
// helpers
// ---------------------------------------------------------------------------
__device__ __forceinline__ uint32_t smem_u32(const void* p) {
    uint32_t a;
    asm("{ .reg .u64 t; cvta.to.shared.u64 t, %1; cvt.u32.u64 %0, t; }"
        : "=r"(a) : "l"(p));
    return a;
}
__device__ __forceinline__ uint32_t pack_bf16x2(float x, float y) {
    __nv_bfloat162 t(__float2bfloat16(x), __float2bfloat16(y));  // x -> low
    return *(uint32_t*)&t;
}
__device__ __forceinline__ void split_bf16(float v, __nv_bfloat16& h, float& lo) {
    h = __float2bfloat16(v);
    lo = v - __bfloat162float(h);
}
// split two floats -> (hi bf16x2, lo bf16x2)
__device__ __forceinline__ void split2(float x, float y, uint32_t& hi, uint32_t& lo) {
    __nv_bfloat16 hx, hy; float lx, ly;
    split_bf16(x, hx, lx); split_bf16(y, hy, ly);
    __nv_bfloat162 H(hx, hy);
    hi = *(uint32_t*)&H;
    lo = pack_bf16x2(lx, ly);
}

// mma.sync m16n8k16 bf16 -> f32 (target-portable PTX, runs on HMMA pipe)
#define MMA4(c, a, b) asm volatile( \
    "mma.sync.aligned.m16n8k16.row.col.f32.bf16.bf16.f32 " \
    "{%0,%1,%2,%3}, {%4,%5,%6,%7}, {%8,%9}, {%0,%1,%2,%3};" \
    : "+f"((c)[0]), "+f"((c)[1]), "+f"((c)[2]), "+f"((c)[3]) \
    : "r"((a)[0]), "r"((a)[1]), "r"((a)[2]), "r"((a)[3]), \
      "r"((b)[0]), "r"((b)[1]))

#define LDS32(x, a) asm volatile("ld.shared.b32 %0, [%1];" : "=r"(x) : "r"(a))
#define CP_ASYNC16(dst, src) \
    asm volatile("cp.async.cg.shared.global [%0], [%1], 16;" \
                 :: "r"(dst), "l"(src) : "memory")
#define CP_COMMIT asm volatile("cp.async.commit_group;" ::: "memory")
#define CP_WAIT(n) asm volatile("cp.async.wait_group %0;" :: "n"(n) : "memory")

// ---------------------------------------------------------------------------
// Weight transpose+split preps (tiny)
// ---------------------------------------------------------------------------
__global__ void prep_w_qkv(const float* __restrict__ wq,
                           const float* __restrict__ wk,
                           const float* __restrict__ wv) {
    int k = blockIdx.x, z = blockIdx.y, n = threadIdx.x;   // 128 thr
    const float* w = (z == 0) ? wq : (z == 1) ? wk : wv;
    float v = w[k * DH + n];
    __nv_bfloat16 h; float lo; split_bf16(v, h, lo);
    size_t o = (size_t)z * DH * DM + (size_t)n * DM + k;
    g_wThi[o] = h; g_wTlo[o] = __float2bfloat16(lo);
}
__global__ void prep_wo(const float* __restrict__ wo) {
    int k = blockIdx.x;                                    // 128 blocks, 256 thr
#pragma unroll
    for (int i = 0; i < 4; i++) {
        int n = threadIdx.x + i * 256;
        float v = wo[(size_t)k * DM + n];
        __nv_bfloat16 h; float lo; split_bf16(v, h, lo);
        g_woThi[(size_t)n * DH + k] = h;
        g_woTlo[(size_t)n * DH + k] = __float2bfloat16(lo);
    }
}

// V transpose+split: g_v[b*SEQ+key][d] (f32) -> g_vt{hi,lo}[b][d][key] (bf16)
// grid (SEQ/64, BATCH), block 256.
__global__ void prep_vt() {
    __shared__ float ts[64][132];
    const int b = blockIdx.y, k0 = blockIdx.x * 64;
    const int tid = threadIdx.x;
#pragma unroll
    for (int i = 0; i < 8; i++) {
        int id = tid + i * 256;
        int r = id >> 5, c = (id & 31) * 4;
        float4 v = *(const float4*)&g_v[((size_t)b * SEQ + k0 + r) * DH + c];
        ts[r][c] = v.x; ts[r][c + 1] = v.y; ts[r][c + 2] = v.z; ts[r][c + 3] = v.w;
    }
    __syncthreads();
    const int d = tid >> 1, h = tid & 1;
    uint32_t* ohi = (uint32_t*)g_vthi + ((((size_t)b * DH + d) * SEQ + k0) >> 1) + h * 16;
    uint32_t* olo = (uint32_t*)g_vtlo + ((((size_t)b * DH + d) * SEQ + k0) >> 1) + h * 16;
#pragma unroll
    for (int j = 0; j < 16; j++) {
        int key = h * 32 + j * 2;
        uint32_t hv, lv;
        split2(ts[key][d], ts[key + 1][d], hv, lv);
        ohi[j] = hv; olo[j] = lv;
    }
}

// ---------------------------------------------------------------------------
// Generic warp-mma GEMM body (as R8), epilogue optionally split-stores bf16.
// ---------------------------------------------------------------------------
#define SA 40
#define SB 40
#define ABYTES (64 * SA * 2)                 // 5120
#define BBYTES (128 * SB * 2)                // 10240
#define BUFB (2 * ABYTES + 2 * BBYTES)       // 30720
#define GEMM_SMEM (2 * BUFB)                 // 61440

__device__ __forceinline__ void gemm_body(
    const float* __restrict__ A, int lda,
    const __nv_bfloat16* __restrict__ Bhig,
    const __nv_bfloat16* __restrict__ Blog, int ldb,
    float* __restrict__ C,
    __nv_bfloat16* __restrict__ Chi, __nv_bfloat16* __restrict__ Clo,
    int ldc, int nc)
{
    extern __shared__ char smg[];
    const int tid  = threadIdx.x;
    const int lane = tid & 31;
    const int wid  = tid >> 5;
    const int warpM = wid >> 2;
    const int warpN = wid & 3;
    const int qr = lane >> 2, qc = lane & 3;

    float acc[2][4][4];
#pragma unroll
    for (int mt = 0; mt < 2; mt++)
#pragma unroll
        for (int nt = 0; nt < 4; nt++)
#pragma unroll
            for (int i = 0; i < 4; i++) acc[mt][nt][i] = 0.f;

    float4 apre[2];
    uint4  bpre[4];
    {
        const int k0 = 0;
#pragma unroll
        for (int i = 0; i < 2; i++) {
            int idx = tid + i * 256, r = idx >> 3, c4 = idx & 7;
            apre[i] = *(const float4*)(A + (size_t)r * lda + k0 + c4 * 4);
        }
        int r = tid >> 1, g = tid & 1;
        const __nv_bfloat16* s = Bhig + (size_t)r * ldb + k0 + g * 16;
        bpre[0] = ((const uint4*)s)[0]; bpre[1] = ((const uint4*)s)[1];
        s = Blog + (size_t)r * ldb + k0 + g * 16;
        bpre[2] = ((const uint4*)s)[0]; bpre[3] = ((const uint4*)s)[1];
    }

    for (int c = 0; c < nc; c++) {
        const int p = c & 1;
        char* buf = smg + p * BUFB;

#pragma unroll
        for (int i = 0; i < 2; i++) {
            int idx = tid + i * 256, r = idx >> 3, c4 = idx & 7;
            float4 v = apre[i];
            uint32_t h0, l0, h1, l1;
            split2(v.x, v.y, h0, l0);
            split2(v.z, v.w, h1, l1);
            *(uint2*)(buf + r * (SA * 2) + c4 * 8) = make_uint2(h0, h1);
            *(uint2*)(buf + ABYTES + r * (SA * 2) + c4 * 8) = make_uint2(l0, l1);
        }
        {
            int r = tid >> 1, g = tid & 1;
            char* d = buf + 2 * ABYTES + r * (SB * 2) + g * 32;
            *(uint4*)(d) = bpre[0];
            *(uint4*)(d + 16) = bpre[1];
            *(uint4*)(d + BBYTES) = bpre[2];
            *(uint4*)(d + BBYTES + 16) = bpre[3];
        }
        __syncthreads();

        if (c + 1 < nc) {
            const int k0 = (c + 1) * 32;
#pragma unroll
            for (int i = 0; i < 2; i++) {
                int idx = tid + i * 256, r = idx >> 3, c4 = idx & 7;
                apre[i] = *(const float4*)(A + (size_t)r * lda + k0 + c4 * 4);
            }
            int r = tid >> 1, g = tid & 1;
            const __nv_bfloat16* s = Bhig + (size_t)r * ldb + k0 + g * 16;
            bpre[0] = ((const uint4*)s)[0]; bpre[1] = ((const uint4*)s)[1];
            s = Blog + (size_t)r * ldb + k0 + g * 16;
            bpre[2] = ((const uint4*)s)[0]; bpre[3] = ((const uint4*)s)[1];
        }

        const char* Ah = buf;
        const char* Al = buf + ABYTES;
        const char* Bh = buf + 2 * ABYTES;
        const char* Bl = buf + 2 * ABYTES + BBYTES;
#pragma unroll
        for (int s = 0; s < 2; s++) {
            const int kb = s * 16 + qc * 2;
            uint32_t ah[2][4], al[2][4], bh[4][2], bl[4][2];
#pragma unroll
            for (int mt = 0; mt < 2; mt++) {
                int r = warpM * 32 + mt * 16 + qr;
                ah[mt][0] = *(const uint32_t*)(Ah + (r * SA + kb) * 2);
                ah[mt][1] = *(const uint32_t*)(Ah + ((r + 8) * SA + kb) * 2);
                ah[mt][2] = *(const uint32_t*)(Ah + (r * SA + kb + 8) * 2);
                ah[mt][3] = *(const uint32_t*)(Ah + ((r + 8) * SA + kb + 8) * 2);
                al[mt][0] = *(const uint32_t*)(Al + (r * SA + kb) * 2);
                al[mt][1] = *(const uint32_t*)(Al + ((r + 8) * SA + kb) * 2);
                al[mt][2] = *(const uint32_t*)(Al + (r * SA + kb + 8) * 2);
                al[mt][3] = *(const uint32_t*)(Al + ((r + 8) * SA + kb + 8) * 2);
            }
#pragma unroll
            for (int nt = 0; nt < 4; nt++) {
                int n = warpN * 32 + nt * 8 + qr;
                bh[nt][0] = *(const uint32_t*)(Bh + (n * SB + kb) * 2);
                bh[nt][1] = *(const uint32_t*)(Bh + (n * SB + kb + 8) * 2);
                bl[nt][0] = *(const uint32_t*)(Bl + (n * SB + kb) * 2);
                bl[nt][1] = *(const uint32_t*)(Bl + (n * SB + kb + 8) * 2);
            }
#pragma unroll
            for (int mt = 0; mt < 2; mt++)
#pragma unroll
                for (int nt = 0; nt < 4; nt++) {
                    MMA4(acc[mt][nt], ah[mt], bh[nt]);
                    MMA4(acc[mt][nt], ah[mt], bl[nt]);
                    MMA4(acc[mt][nt], al[mt], bh[nt]);
                }
        }
        __syncthreads();
    }

#pragma unroll
    for (int mt = 0; mt < 2; mt++)
#pragma unroll
        for (int nt = 0; nt < 4; nt++) {
            int r = warpM * 32 + mt * 16 + qr;
            int col = warpN * 32 + nt * 8 + qc * 2;
            if (Chi) {
                uint32_t h0, l0, h1, l1;
                split2(acc[mt][nt][0], acc[mt][nt][1], h0, l0);
                split2(acc[mt][nt][2], acc[mt][nt][3], h1, l1);
                ((uint32_t*)(Chi + (size_t)r * ldc))[col >> 1] = h0;
                ((uint32_t*)(Clo + (size_t)r * ldc))[col >> 1] = l0;
                ((uint32_t*)(Chi + (size_t)(r + 8) * ldc))[col >> 1] = h1;
                ((uint32_t*)(Clo + (size_t)(r + 8) * ldc))[col >> 1] = l1;
            } else {
                *(float2*)(C + (size_t)r * ldc + col) =
                    make_float2(acc[mt][nt][0], acc[mt][nt][1]);
                *(float2*)(C + (size_t)(r + 8) * ldc + col) =
                    make_float2(acc[mt][nt][2], acc[mt][nt][3]);
            }
        }
}

// qkv: grid (128, 3): 64 rows per CTA, K=1024 (nc=32), N=128.
// z=0 -> Q hi/lo, z=1 -> K hi/lo, z=2 -> V f32.
__global__ __launch_bounds__(256, 2) void qkv_mma_kernel(const float* __restrict__ x) {
    const int z = blockIdx.y, bx = blockIdx.x;
    const __nv_bfloat16* Bh = g_wThi + (size_t)z * DH * DM;
    const __nv_bfloat16* Bl = g_wTlo + (size_t)z * DH * DM;
    const size_t rb = (size_t)bx * 64;
    float* C = nullptr; __nv_bfloat16 *Chi = nullptr, *Clo = nullptr;
    if (z == 0)      { Chi = g_qhi + rb * DH; Clo = g_qlo + rb * DH; }
    else if (z == 1) { Chi = g_khi + rb * DH; Clo = g_klo + rb * DH; }
    else             { C = g_v + rb * DH; }
    gemm_body(x + rb * DM, DM, Bh, Bl, DM, C, Chi, Clo, DH, 32);
}

// out: grid (128, 8): 64 rows, n-slab 128, K=128 (nc=4).
__global__ __launch_bounds__(256, 2) void out_mma_kernel(float* __restrict__ out) {
    const int bx = blockIdx.x, by = blockIdx.y;
    const __nv_bfloat16* Bh = g_woThi + (size_t)by * 128 * DH;
    const __nv_bfloat16* Bl = g_woTlo + (size_t)by * 128 * DH;
    float* C = out + (size_t)bx * 64 * DM + by * 128;
    gemm_body(g_ctx + (size_t)bx * 64 * DH, DH, Bh, Bl, DH, C, nullptr, nullptr, DM, 4);
}

// ---------------------------------------------------------------------------
// Tensor-core causal flash attention.
// BQ=64, BK=64. 128 threads = 4 warps; warp w owns q-rows w*16..w*16+15.
// Double-buffered cp.async K/V tiles; S and PV via bf16 hi/lo mma.sync.
// grid = (BATCH*32); smem = 178176 B.
// ---------------------------------------------------------------------------
#define ATTN_SMEM 178176
// smem byte offsets (within dynamic smem)
//   Qhi @ 0       (64 rows * 272B)
//   Qlo @ 17408
//   buf p @ 34816 + p*71680:  Khi +0, Klo +17408, Vthi +34816, Vtlo +53248
//   K rows: 272B stride; Vt rows: 144B stride.

__device__ __forceinline__ void attn_issue_tile(
    uint32_t sbase, int tid, int b, int kt, int p, size_t bbase)
{
    const uint32_t base = sbase + 34816 + p * 71680;
    const int k0 = kt * 64;
    const char* khi_g = (const char*)(g_khi + (bbase + k0) * DH);
    const char* klo_g = (const char*)(g_klo + (bbase + k0) * DH);
    const char* vhi_g = (const char*)g_vthi + (((size_t)b * DH) * SEQ + k0) * 2;
    const char* vlo_g = (const char*)g_vtlo + (((size_t)b * DH) * SEQ + k0) * 2;
#pragma unroll
    for (int i = 0; i < 8; i++) {
        int id = tid + i * 128;                 // 0..1023
        int r  = id >> 4, off  = (id & 15) * 16;   // K: 64 rows x 256B
        CP_ASYNC16(base + r * 272 + off, khi_g + (size_t)r * 256 + off);
        CP_ASYNC16(base + 17408 + r * 272 + off, klo_g + (size_t)r * 256 + off);
        int rv = id >> 3, offv = (id & 7) * 16;    // Vt: 128 rows x 128B
        CP_ASYNC16(base + 34816 + rv * 144 + offv,
                   vhi_g + (size_t)rv * (SEQ * 2) + offv);
        CP_ASYNC16(base + 53248 + rv * 144 + offv,
                   vlo_g + (size_t)rv * (SEQ * 2) + offv);
    }
}

__global__ __launch_bounds__(128, 1) void attn_mma_kernel()
{
    extern __shared__ char sm[];
    const uint32_t sbase = smem_u32(sm);
    const int tid  = threadIdx.x;
    const int lane = tid & 31;
    const int wq   = tid >> 5;            // warp 0..3 -> q rows wq*16..+15
    const int qr   = lane >> 2, qc = lane & 3;
    const int b    = blockIdx.x >> 5;
    const int qt   = blockIdx.x & 31;
    const int qb   = qt * 64;
    const size_t bbase = (size_t)b * SEQ;
    const int ntiles = qt + 1;
    const float scale = 0.08838834764831845f;   // 1/sqrt(128)

    // ---- issue Q load + tile 0 (one group) ----
    {
        const char* qhi_g = (const char*)(g_qhi + (bbase + qb) * DH);
        const char* qlo_g = (const char*)(g_qlo + (bbase + qb) * DH);
#pragma unroll
        for (int i = 0; i < 8; i++) {
            int id = tid + i * 128;
            int r = id >> 4, off = (id & 15) * 16;
            CP_ASYNC16(sbase + r * 272 + off, qhi_g + (size_t)r * 256 + off);
            CP_ASYNC16(sbase + 17408 + r * 272 + off, qlo_g + (size_t)r * 256 + off);
        }
        attn_issue_tile(sbase, tid, b, 0, 0, bbase);
        CP_COMMIT;
    }

    float O[16][4];
#pragma unroll
    for (int nf = 0; nf < 16; nf++)
#pragma unroll
        for (int i = 0; i < 4; i++) O[nf][i] = 0.f;
    float m0 = -1e30f, m1 = -1e30f, l0 = 0.f, l1 = 0.f;

    for (int kt = 0; kt < ntiles; kt++) {
        const int p = kt & 1;
        if (kt + 1 < ntiles) {
            attn_issue_tile(sbase, tid, b, kt + 1, p ^ 1, bbase);
            CP_COMMIT;
            CP_WAIT(1);
        } else {
            CP_WAIT(0);
        }
        __syncthreads();

        const uint32_t base = sbase + 34816 + p * 71680;
        const uint32_t sK  = base, sKlo = base + 17408;
        const uint32_t sV  = base + 34816, sVlo = base + 53248;

        // ---- S = Q K^T (hi/lo x hi/lo, 3 products) ----
        float sacc[8][4];
#pragma unroll
        for (int nf = 0; nf < 8; nf++)
#pragma unroll
            for (int i = 0; i < 4; i++) sacc[nf][i] = 0.f;

#pragma unroll
        for (int kf = 0; kf < 8; kf++) {
            const int qrow = wq * 16 + qr;
            const uint32_t qa = sbase + qrow * 272 + kf * 32 + qc * 4;
            uint32_t ah[4], al[4];
            LDS32(ah[0], qa);          LDS32(ah[1], qa + 2176);
            LDS32(ah[2], qa + 16);     LDS32(ah[3], qa + 2176 + 16);
            LDS32(al[0], qa + 17408);  LDS32(al[1], qa + 17408 + 2176);
            LDS32(al[2], qa + 17408 + 16); LDS32(al[3], qa + 17408 + 2176 + 16);
#pragma unroll
            for (int nf = 0; nf < 8; nf++) {
                const uint32_t ka = (nf * 8 + qr) * 272 + kf * 32 + qc * 4;
                uint32_t bh[2], bl[2];
                LDS32(bh[0], sK + ka);   LDS32(bh[1], sK + ka + 16);
                LDS32(bl[0], sKlo + ka); LDS32(bl[1], sKlo + ka + 16);
                MMA4(sacc[nf], ah, bh);
                MMA4(sacc[nf], ah, bl);
                MMA4(sacc[nf], al, bh);
            }
        }

        // ---- scale + causal mask (diagonal tile only) ----
#pragma unroll
        for (int nf = 0; nf < 8; nf++)
#pragma unroll
            for (int i = 0; i < 4; i++) sacc[nf][i] *= scale;
        if (kt == qt) {
            const int q0 = wq * 16 + qr, q1 = q0 + 8;
#pragma unroll
            for (int nf = 0; nf < 8; nf++) {
                const int key = nf * 8 + qc * 2;
                if (key > q0)     sacc[nf][0] = -1e30f;
                if (key + 1 > q0) sacc[nf][1] = -1e30f;
                if (key > q1)     sacc[nf][2] = -1e30f;
                if (key + 1 > q1) sacc[nf][3] = -1e30f;
            }
        }

        // ---- online softmax on fragments (4-lane row groups) ----
        float mt0 = -1e30f, mt1 = -1e30f;
#pragma unroll
        for (int nf = 0; nf < 8; nf++) {
            mt0 = fmaxf(mt0, fmaxf(sacc[nf][0], sacc[nf][1]));
            mt1 = fmaxf(mt1, fmaxf(sacc[nf][2], sacc[nf][3]));
        }
        mt0 = fmaxf(mt0, __shfl_xor_sync(0xffffffffu, mt0, 1));
        mt0 = fmaxf(mt0, __shfl_xor_sync(0xffffffffu, mt0, 2));
        mt1 = fmaxf(mt1, __shfl_xor_sync(0xffffffffu, mt1, 1));
        mt1 = fmaxf(mt1, __shfl_xor_sync(0xffffffffu, mt1, 2));
        const float nm0 = fmaxf(m0, mt0), nm1 = fmaxf(m1, mt1);
        const float corr0 = __expf(m0 - nm0), corr1 = __expf(m1 - nm1);
        m0 = nm0; m1 = nm1;

        float rs0 = 0.f, rs1 = 0.f;
#pragma unroll
        for (int nf = 0; nf < 8; nf++) {
            sacc[nf][0] = __expf(sacc[nf][0] - nm0);
            sacc[nf][1] = __expf(sacc[nf][1] - nm0);
            sacc[nf][2] = __expf(sacc[nf][2] - nm1);
            sacc[nf][3] = __expf(sacc[nf][3] - nm1);
            rs0 += sacc[nf][0] + sacc[nf][1];
            rs1 += sacc[nf][2] + sacc[nf][3];
        }
        rs0 += __shfl_xor_sync(0xffffffffu, rs0, 1);
        rs0 += __shfl_xor_sync(0xffffffffu, rs0, 2);
        rs1 += __shfl_xor_sync(0xffffffffu, rs1, 1);
        rs1 += __shfl_xor_sync(0xffffffffu, rs1, 2);
        l0 = l0 * corr0 + rs0;
        l1 = l1 * corr1 + rs1;
#pragma unroll
        for (int nf = 0; nf < 16; nf++) {
            O[nf][0] *= corr0; O[nf][1] *= corr0;
            O[nf][2] *= corr1; O[nf][3] *= corr1;
        }

        // ---- O += P V  (P hi/lo from registers, V hi/lo from smem) ----
#pragma unroll
        for (int kv = 0; kv < 4; kv++) {
            uint32_t ah[4], al[4];
            split2(sacc[2 * kv][0],     sacc[2 * kv][1],     ah[0], al[0]);
            split2(sacc[2 * kv][2],     sacc[2 * kv][3],     ah[1], al[1]);
            split2(sacc[2 * kv + 1][0], sacc[2 * kv + 1][1], ah[2], al[2]);
            split2(sacc[2 * kv + 1][2], sacc[2 * kv + 1][3], ah[3], al[3]);
#pragma unroll
            for (int nf = 0; nf < 16; nf++) {
                const uint32_t va = (nf * 8 + qr) * 144 + kv * 32 + qc * 4;
                uint32_t bh[2], bl[2];
                LDS32(bh[0], sV + va);   LDS32(bh[1], sV + va + 16);
                LDS32(bl[0], sVlo + va); LDS32(bl[1], sVlo + va + 16);
                MMA4(O[nf], ah, bh);
                MMA4(O[nf], ah, bl);
                MMA4(O[nf], al, bh);
            }
        }
        __syncthreads();   // buffer p free for reuse at next issue
    }

    // ---- write ctx ----
    const float inv0 = 1.f / l0, inv1 = 1.f / l1;
    const size_t row0 = bbase + qb + wq * 16 + qr;
#pragma unroll
    for (int nf = 0; nf < 16; nf++) {
        const int col = nf * 8 + qc * 2;
        *(float2*)&g_ctx[row0 * DH + col] =
            make_float2(O[nf][0] * inv0, O[nf][1] * inv0);
        *(float2*)&g_ctx[(row0 + 8) * DH + col] =
            make_float2(O[nf][2] * inv1, O[nf][3] * inv1);
    }
}

// ---------------------------------------------------------------------------
extern "C" void kernel_launch(void* const* d_in, const int* in_sizes, int n_in,
                              void* d_out, int out_size)
{
    (void)in_sizes; (void)n_in; (void)out_size;
    const float* x  = (const float*)d_in[0];
    const float* wq = (const float*)d_in[1];
    const float* wk = (const float*)d_in[2];
    const float* wv = (const float*)d_in[3];
    const float* wo = (const float*)d_in[4];
    float* out = (float*)d_out;

    cudaFuncSetAttribute(qkv_mma_kernel,
                         cudaFuncAttributeMaxDynamicSharedMemorySize, GEMM_SMEM);
    cudaFuncSetAttribute(out_mma_kernel,
                         cudaFuncAttributeMaxDynamicSharedMemorySize, GEMM_SMEM);
    cudaFuncSetAttribute(attn_mma_kernel,
                         cudaFuncAttributeMaxDynamicSharedMemorySize, ATTN_SMEM);

    prep_w_qkv<<<dim3(DM, 3), DH>>>(wq, wk, wv);
    prep_wo<<<DH, 256>>>(wo);
    qkv_mma_kernel<<<dim3(ROWS / 64, 3), 256, GEMM_SMEM>>>(x);
    prep_vt<<<dim3(SEQ / 64, BATCH), 256>>>();
    attn_mma_kernel<<<BATCH * 32, 128, ATTN_SMEM>>>();
    out_mma_kernel<<<dim3(ROWS / 64, DM / 128), 256, GEMM_SMEM>>>(out);
}

// round 11
// speedup vs baseline: 3.6297x; 1.0666x over previous
#include <cuda_runtime.h>
#include <cuda_bf16.h>
#include <cstdint>

#define BATCH 4
#define SEQ 2048
#define DM 1024
#define DH 128
#define ROWS (BATCH * SEQ)   // 8192

// ---------------------------------------------------------------------------
// Scratch (__device__ globals per allocation rules)
// ---------------------------------------------------------------------------
__device__ __align__(16) float g_v[ROWS * DH];      // V f32 (feeds transpose)
// pre-split bf16 hi/lo activations
__device__ __align__(16) __nv_bfloat16 g_xhi[ROWS * DM];
__device__ __align__(16) __nv_bfloat16 g_xlo[ROWS * DM];
__device__ __align__(16) __nv_bfloat16 g_qhi[ROWS * DH];
__device__ __align__(16) __nv_bfloat16 g_qlo[ROWS * DH];
__device__ __align__(16) __nv_bfloat16 g_khi[ROWS * DH];
__device__ __align__(16) __nv_bfloat16 g_klo[ROWS * DH];
__device__ __align__(16) __nv_bfloat16 g_vthi[BATCH * DH * SEQ];  // [b][d][key]
__device__ __align__(16) __nv_bfloat16 g_vtlo[BATCH * DH * SEQ];
__device__ __align__(16) __nv_bfloat16 g_ctxhi[ROWS * DH];
__device__ __align__(16) __nv_bfloat16 g_ctxlo[ROWS * DH];
// transposed bf16 hi/lo weights: wT[z][n][k] = w_z[k][n]
__device__ __align__(16) __nv_bfloat16 g_wThi[3 * DH * DM];
__device__ __align__(16) __nv_bfloat16 g_wTlo[3 * DH * DM];
__device__ __align__(16) __nv_bfloat16 g_woThi[DM * DH];
__device__ __align__(16) __nv_bfloat16 g_woTlo[DM * DH];

// ---------------------------------------------------------------------------
// helpers
// ---------------------------------------------------------------------------
__device__ __forceinline__ uint32_t smem_u32(const void* p) {
    uint32_t a;
    asm("{ .reg .u64 t; cvta.to.shared.u64 t, %1; cvt.u32.u64 %0, t; }"
        : "=r"(a) : "l"(p));
    return a;
}
__device__ __forceinline__ uint32_t pack_bf16x2(float x, float y) {
    __nv_bfloat162 t(__float2bfloat16(x), __float2bfloat16(y));  // x -> low
    return *(uint32_t*)&t;
}
__device__ __forceinline__ void split_bf16(float v, __nv_bfloat16& h, float& lo) {
    h = __float2bfloat16(v);
    lo = v - __bfloat162float(h);
}
__device__ __forceinline__ void split2(float x, float y, uint32_t& hi, uint32_t& lo) {
    __nv_bfloat16 hx, hy; float lx, ly;
    split_bf16(x, hx, lx); split_bf16(y, hy, ly);
    __nv_bfloat162 H(hx, hy);
    hi = *(uint32_t*)&H;
    lo = pack_bf16x2(lx, ly);
}

// mma.sync m16n8k16 bf16 -> f32 (HMMA pipe, target-portable)
#define MMA4(c, a, b) asm volatile( \
    "mma.sync.aligned.m16n8k16.row.col.f32.bf16.bf16.f32 " \
    "{%0,%1,%2,%3}, {%4,%5,%6,%7}, {%8,%9}, {%0,%1,%2,%3};" \
    : "+f"((c)[0]), "+f"((c)[1]), "+f"((c)[2]), "+f"((c)[3]) \
    : "r"((a)[0]), "r"((a)[1]), "r"((a)[2]), "r"((a)[3]), \
      "r"((b)[0]), "r"((b)[1]))

// ldmatrix x4: four 8x8 b16 tiles; lane l supplies row addr:
//   lanes 0-7 -> m0, 8-15 -> m1, 16-23 -> m2, 24-31 -> m3
#define LDMX4(d, a) asm volatile( \
    "ldmatrix.sync.aligned.m8n8.x4.shared.b16 {%0,%1,%2,%3}, [%4];" \
    : "=r"((d)[0]), "=r"((d)[1]), "=r"((d)[2]), "=r"((d)[3]) : "r"(a))

#define CP_ASYNC16(dst, src) \
    asm volatile("cp.async.cg.shared.global [%0], [%1], 16;" \
                 :: "r"(dst), "l"(src) : "memory")
#define CP_COMMIT asm volatile("cp.async.commit_group;" ::: "memory")
#define CP_WAIT(n) asm volatile("cp.async.wait_group %0;" :: "n"(n) : "memory")

// ---------------------------------------------------------------------------
// Prep kernels
// ---------------------------------------------------------------------------
// split X once: x f32 -> g_xhi/g_xlo. grid ROWS*DM/1024, 256 thr, 4 el/thr.
__global__ void prep_x(const float* __restrict__ x) {
    size_t base = ((size_t)blockIdx.x * 256 + threadIdx.x) * 4;
    float4 v = *(const float4*)(x + base);
    uint32_t h0, l0, h1, l1;
    split2(v.x, v.y, h0, l0);
    split2(v.z, v.w, h1, l1);
    *(uint2*)((char*)g_xhi + base * 2) = make_uint2(h0, h1);
    *(uint2*)((char*)g_xlo + base * 2) = make_uint2(l0, l1);
}

__global__ void prep_w_qkv(const float* __restrict__ wq,
                           const float* __restrict__ wk,
                           const float* __restrict__ wv) {
    int k = blockIdx.x, z = blockIdx.y, n = threadIdx.x;   // 128 thr
    const float* w = (z == 0) ? wq : (z == 1) ? wk : wv;
    float v = w[k * DH + n];
    __nv_bfloat16 h; float lo; split_bf16(v, h, lo);
    size_t o = (size_t)z * DH * DM + (size_t)n * DM + k;
    g_wThi[o] = h; g_wTlo[o] = __float2bfloat16(lo);
}
__global__ void prep_wo(const float* __restrict__ wo) {
    int k = blockIdx.x;                                    // 128 blocks, 256 thr
#pragma unroll
    for (int i = 0; i < 4; i++) {
        int n = threadIdx.x + i * 256;
        float v = wo[(size_t)k * DM + n];
        __nv_bfloat16 h; float lo; split_bf16(v, h, lo);
        g_woThi[(size_t)n * DH + k] = h;
        g_woTlo[(size_t)n * DH + k] = __float2bfloat16(lo);
    }
}

// V transpose+split: g_v[b*SEQ+key][d] (f32) -> g_vt{hi,lo}[b][d][key] (bf16)
__global__ void prep_vt() {
    __shared__ float ts[64][132];
    const int b = blockIdx.y, k0 = blockIdx.x * 64;
    const int tid = threadIdx.x;
#pragma unroll
    for (int i = 0; i < 8; i++) {
        int id = tid + i * 256;
        int r = id >> 5, c = (id & 31) * 4;
        float4 v = *(const float4*)&g_v[((size_t)b * SEQ + k0 + r) * DH + c];
        ts[r][c] = v.x; ts[r][c + 1] = v.y; ts[r][c + 2] = v.z; ts[r][c + 3] = v.w;
    }
    __syncthreads();
    const int d = tid >> 1, h = tid & 1;
    uint32_t* ohi = (uint32_t*)g_vthi + ((((size_t)b * DH + d) * SEQ + k0) >> 1) + h * 16;
    uint32_t* olo = (uint32_t*)g_vtlo + ((((size_t)b * DH + d) * SEQ + k0) >> 1) + h * 16;
#pragma unroll
    for (int j = 0; j < 16; j++) {
        int key = h * 32 + j * 2;
        uint32_t hv, lv;
        split2(ts[key][d], ts[key + 1][d], hv, lv);
        ohi[j] = hv; olo[j] = lv;
    }
}

// ---------------------------------------------------------------------------
// Generic warp-mma GEMM body. A and B are PRE-SPLIT bf16 hi/lo.
// C[64, 128] = A[64, K] x B[n][k];  BK=32 chunks, cp.async double buffer.
// 8 warps (2m x 4n); warp tile 32x32; ldmatrix fragment loads.
// smem/buffer: Ahi[64][40] Alo Bhi[128][40] Blo (stride 40 halves = 80B).
// ---------------------------------------------------------------------------
#define ABY  5120                             // 64*80
#define BBY  10240                            // 128*80
#define BUFB (2 * ABY + 2 * BBY)              // 30720
#define GEMM_SMEM (2 * BUFB)                  // 61440

__device__ __forceinline__ void gemm_body(
    const __nv_bfloat16* __restrict__ Ahi,
    const __nv_bfloat16* __restrict__ Alo, int lda,
    const __nv_bfloat16* __restrict__ Bhig,
    const __nv_bfloat16* __restrict__ Blog, int ldb,
    float* __restrict__ C,
    __nv_bfloat16* __restrict__ Chi, __nv_bfloat16* __restrict__ Clo,
    int ldc, int nc)
{
    extern __shared__ char smg[];
    const uint32_t sbase = smem_u32(smg);
    const int tid  = threadIdx.x;
    const int lane = tid & 31;
    const int wid  = tid >> 5;
    const int warpM = wid >> 2;
    const int warpN = wid & 3;
    const int qr = lane >> 2, qc = lane & 3;

    float acc[2][4][4];
#pragma unroll
    for (int mt = 0; mt < 2; mt++)
#pragma unroll
        for (int nt = 0; nt < 4; nt++)
#pragma unroll
            for (int i = 0; i < 4; i++) acc[mt][nt][i] = 0.f;

    // cp.async issue of chunk c into buffer p
    auto issue = [&](int c, int p) {
        const uint32_t bufb = sbase + p * BUFB;
#pragma unroll
        for (int i = 0; i < 2; i++) {               // A: 512 x 16B
            int u = tid + i * 256;
            int r = u >> 3, cc = u & 3, hf = (u >> 2) & 1;
            uint32_t dst = bufb + (hf ? ABY : 0) + r * 80 + cc * 16;
            const char* src = (const char*)((hf ? Alo : Ahi) +
                                            (size_t)r * lda + c * 32 + cc * 8);
            CP_ASYNC16(dst, src);
        }
#pragma unroll
        for (int i = 0; i < 4; i++) {               // B: 1024 x 16B
            int u = tid + i * 256;
            int r = u >> 3, cc = u & 3, hf = (u >> 2) & 1;
            uint32_t dst = bufb + 2 * ABY + (hf ? BBY : 0) + r * 80 + cc * 16;
            const char* src = (const char*)((hf ? Blog : Bhig) +
                                            (size_t)r * ldb + c * 32 + cc * 8);
            CP_ASYNC16(dst, src);
        }
    };

    issue(0, 0); CP_COMMIT;

    // per-lane ldmatrix row-address offsets (within buffer)
    const uint32_t aoff_hi = (warpM * 32 + (lane & 15)) * 80 + ((lane >> 4) & 1) * 16;
    const uint32_t aoff_lo = aoff_hi + ABY;
    const uint32_t boff = 2 * ABY + ((lane & 16) ? BBY : 0) +
                          (warpN * 32 + (lane & 7)) * 80 + ((lane >> 3) & 1) * 16;

    for (int c = 0; c < nc; c++) {
        const int p = c & 1;
        if (c + 1 < nc) { issue(c + 1, p ^ 1); CP_COMMIT; CP_WAIT(1); }
        else            { CP_WAIT(0); }
        __syncthreads();

        const uint32_t bufb = sbase + p * BUFB;
#pragma unroll
        for (int s = 0; s < 2; s++) {
            uint32_t ah[2][4], al[2][4];
#pragma unroll
            for (int mt = 0; mt < 2; mt++) {
                LDMX4(ah[mt], bufb + aoff_hi + mt * 16 * 80 + s * 32);
                LDMX4(al[mt], bufb + aoff_lo + mt * 16 * 80 + s * 32);
            }
#pragma unroll
            for (int nt = 0; nt < 4; nt++) {
                uint32_t bb[4];
                LDMX4(bb, bufb + boff + nt * 8 * 80 + s * 32);
                uint32_t bh[2] = {bb[0], bb[1]}, bl[2] = {bb[2], bb[3]};
#pragma unroll
                for (int mt = 0; mt < 2; mt++) {
                    MMA4(acc[mt][nt], ah[mt], bh);
                    MMA4(acc[mt][nt], ah[mt], bl);
                    MMA4(acc[mt][nt], al[mt], bh);
                }
            }
        }
        __syncthreads();
    }

#pragma unroll
    for (int mt = 0; mt < 2; mt++)
#pragma unroll
        for (int nt = 0; nt < 4; nt++) {
            int r = warpM * 32 + mt * 16 + qr;
            int col = warpN * 32 + nt * 8 + qc * 2;
            if (Chi) {
                uint32_t h0, l0, h1, l1;
                split2(acc[mt][nt][0], acc[mt][nt][1], h0, l0);
                split2(acc[mt][nt][2], acc[mt][nt][3], h1, l1);
                ((uint32_t*)(Chi + (size_t)r * ldc))[col >> 1] = h0;
                ((uint32_t*)(Clo + (size_t)r * ldc))[col >> 1] = l0;
                ((uint32_t*)(Chi + (size_t)(r + 8) * ldc))[col >> 1] = h1;
                ((uint32_t*)(Clo + (size_t)(r + 8) * ldc))[col >> 1] = l1;
            } else {
                *(float2*)(C + (size_t)r * ldc + col) =
                    make_float2(acc[mt][nt][0], acc[mt][nt][1]);
                *(float2*)(C + (size_t)(r + 8) * ldc + col) =
                    make_float2(acc[mt][nt][2], acc[mt][nt][3]);
            }
        }
}

// qkv: grid (128, 3): 64 rows/CTA, K=1024 (nc=32), N=128.
// z=0 -> Q hi/lo, z=1 -> K hi/lo, z=2 -> V f32.
__global__ __launch_bounds__(256, 2) void qkv_mma_kernel() {
    const int z = blockIdx.y, bx = blockIdx.x;
    const __nv_bfloat16* Bh = g_wThi + (size_t)z * DH * DM;
    const __nv_bfloat16* Bl = g_wTlo + (size_t)z * DH * DM;
    const size_t rb = (size_t)bx * 64;
    float* C = nullptr; __nv_bfloat16 *Chi = nullptr, *Clo = nullptr;
    if (z == 0)      { Chi = g_qhi + rb * DH; Clo = g_qlo + rb * DH; }
    else if (z == 1) { Chi = g_khi + rb * DH; Clo = g_klo + rb * DH; }
    else             { C = g_v + rb * DH; }
    gemm_body(g_xhi + rb * DM, g_xlo + rb * DM, DM, Bh, Bl, DM, C, Chi, Clo, DH, 32);
}

// out: grid (128, 8): 64 rows, n-slab 128, K=128 (nc=4). A = ctx hi/lo.
__global__ __launch_bounds__(256, 2) void out_mma_kernel(float* __restrict__ out) {
    const int bx = blockIdx.x, by = blockIdx.y;
    const __nv_bfloat16* Bh = g_woThi + (size_t)by * 128 * DH;
    const __nv_bfloat16* Bl = g_woTlo + (size_t)by * 128 * DH;
    float* C = out + (size_t)bx * 64 * DM + by * 128;
    gemm_body(g_ctxhi + (size_t)bx * 64 * DH, g_ctxlo + (size_t)bx * 64 * DH, DH,
              Bh, Bl, DH, C, nullptr, nullptr, DM, 4);
}

// ---------------------------------------------------------------------------
// Tensor-core causal flash attention (BQ=64, BK=64, 4 warps), ldmatrix loads.
// smem: Qhi@0 (64x272B), Qlo@17408, buf p @34816+p*71680:
//       Khi+0, Klo+17408, Vthi+34816, Vtlo+53248; K stride 272B, Vt 144B.
// ---------------------------------------------------------------------------
#define ATTN_SMEM 178176

__device__ __forceinline__ void attn_issue_tile(
    uint32_t sbase, int tid, int b, int kt, int p, size_t bbase)
{
    const uint32_t base = sbase + 34816 + p * 71680;
    const int k0 = kt * 64;
    const char* khi_g = (const char*)(g_khi + (bbase + k0) * DH);
    const char* klo_g = (const char*)(g_klo + (bbase + k0) * DH);
    const char* vhi_g = (const char*)g_vthi + (((size_t)b * DH) * SEQ + k0) * 2;
    const char* vlo_g = (const char*)g_vtlo + (((size_t)b * DH) * SEQ + k0) * 2;
#pragma unroll
    for (int i = 0; i < 8; i++) {
        int id = tid + i * 128;
        int r  = id >> 4, off  = (id & 15) * 16;   // K: 64 rows x 256B
        CP_ASYNC16(base + r * 272 + off, khi_g + (size_t)r * 256 + off);
        CP_ASYNC16(base + 17408 + r * 272 + off, klo_g + (size_t)r * 256 + off);
        int rv = id >> 3, offv = (id & 7) * 16;    // Vt: 128 rows x 128B
        CP_ASYNC16(base + 34816 + rv * 144 + offv,
                   vhi_g + (size_t)rv * (SEQ * 2) + offv);
        CP_ASYNC16(base + 53248 + rv * 144 + offv,
                   vlo_g + (size_t)rv * (SEQ * 2) + offv);
    }
}

__global__ __launch_bounds__(128, 1) void attn_mma_kernel()
{
    extern __shared__ char sm[];
    const uint32_t sbase = smem_u32(sm);
    const int tid  = threadIdx.x;
    const int lane = tid & 31;
    const int wq   = tid >> 5;
    const int qr   = lane >> 2, qc = lane & 3;
    const int b    = blockIdx.x >> 5;
    const int qt   = blockIdx.x & 31;
    const int qb   = qt * 64;
    const size_t bbase = (size_t)b * SEQ;
    const int ntiles = qt + 1;
    const float scale = 0.08838834764831845f;

    {
        const char* qhi_g = (const char*)(g_qhi + (bbase + qb) * DH);
        const char* qlo_g = (const char*)(g_qlo + (bbase + qb) * DH);
#pragma unroll
        for (int i = 0; i < 8; i++) {
            int id = tid + i * 128;
            int r = id >> 4, off = (id & 15) * 16;
            CP_ASYNC16(sbase + r * 272 + off, qhi_g + (size_t)r * 256 + off);
            CP_ASYNC16(sbase + 17408 + r * 272 + off, qlo_g + (size_t)r * 256 + off);
        }
        attn_issue_tile(sbase, tid, b, 0, 0, bbase);
        CP_COMMIT;
    }

    // per-lane ldmatrix row addresses
    const uint32_t q_hi_addr = sbase + (wq * 16 + (lane & 15)) * 272 +
                               ((lane >> 4) & 1) * 16;
    const uint32_t q_lo_addr = q_hi_addr + 17408;
    const uint32_t k_off = ((lane & 16) ? 17408u : 0u) +
                           (lane & 7) * 272 + ((lane >> 3) & 1) * 16;
    const uint32_t v_off = 34816u + ((lane & 16) ? 18432u : 0u) +
                           (lane & 7) * 144 + ((lane >> 3) & 1) * 16;

    float O[16][4];
#pragma unroll
    for (int nf = 0; nf < 16; nf++)
#pragma unroll
        for (int i = 0; i < 4; i++) O[nf][i] = 0.f;
    float m0 = -1e30f, m1 = -1e30f, l0 = 0.f, l1 = 0.f;

    for (int kt = 0; kt < ntiles; kt++) {
        const int p = kt & 1;
        if (kt + 1 < ntiles) {
            attn_issue_tile(sbase, tid, b, kt + 1, p ^ 1, bbase);
            CP_COMMIT;
            CP_WAIT(1);
        } else {
            CP_WAIT(0);
        }
        __syncthreads();

        const uint32_t base = sbase + 34816 + p * 71680;

        // ---- S = Q K^T ----
        float sacc[8][4];
#pragma unroll
        for (int nf = 0; nf < 8; nf++)
#pragma unroll
            for (int i = 0; i < 4; i++) sacc[nf][i] = 0.f;

#pragma unroll
        for (int kf = 0; kf < 8; kf++) {
            uint32_t ah[4], al[4];
            LDMX4(ah, q_hi_addr + kf * 32);
            LDMX4(al, q_lo_addr + kf * 32);
#pragma unroll
            for (int nf = 0; nf < 8; nf++) {
                uint32_t bb[4];
                LDMX4(bb, base + k_off + nf * 2176 + kf * 32);
                uint32_t bh[2] = {bb[0], bb[1]}, bl[2] = {bb[2], bb[3]};
                MMA4(sacc[nf], ah, bh);
                MMA4(sacc[nf], ah, bl);
                MMA4(sacc[nf], al, bh);
            }
        }

        // ---- scale + causal mask ----
#pragma unroll
        for (int nf = 0; nf < 8; nf++)
#pragma unroll
            for (int i = 0; i < 4; i++) sacc[nf][i] *= scale;
        if (kt == qt) {
            const int q0 = wq * 16 + qr, q1 = q0 + 8;
#pragma unroll
            for (int nf = 0; nf < 8; nf++) {
                const int key = nf * 8 + qc * 2;
                if (key > q0)     sacc[nf][0] = -1e30f;
                if (key + 1 > q0) sacc[nf][1] = -1e30f;
                if (key > q1)     sacc[nf][2] = -1e30f;
                if (key + 1 > q1) sacc[nf][3] = -1e30f;
            }
        }

        // ---- online softmax ----
        float mt0 = -1e30f, mt1 = -1e30f;
#pragma unroll
        for (int nf = 0; nf < 8; nf++) {
            mt0 = fmaxf(mt0, fmaxf(sacc[nf][0], sacc[nf][1]));
            mt1 = fmaxf(mt1, fmaxf(sacc[nf][2], sacc[nf][3]));
        }
        mt0 = fmaxf(mt0, __shfl_xor_sync(0xffffffffu, mt0, 1));
        mt0 = fmaxf(mt0, __shfl_xor_sync(0xffffffffu, mt0, 2));
        mt1 = fmaxf(mt1, __shfl_xor_sync(0xffffffffu, mt1, 1));
        mt1 = fmaxf(mt1, __shfl_xor_sync(0xffffffffu, mt1, 2));
        const float nm0 = fmaxf(m0, mt0), nm1 = fmaxf(m1, mt1);
        const float corr0 = __expf(m0 - nm0), corr1 = __expf(m1 - nm1);
        m0 = nm0; m1 = nm1;

        float rs0 = 0.f, rs1 = 0.f;
#pragma unroll
        for (int nf = 0; nf < 8; nf++) {
            sacc[nf][0] = __expf(sacc[nf][0] - nm0);
            sacc[nf][1] = __expf(sacc[nf][1] - nm0);
            sacc[nf][2] = __expf(sacc[nf][2] - nm1);
            sacc[nf][3] = __expf(sacc[nf][3] - nm1);
            rs0 += sacc[nf][0] + sacc[nf][1];
            rs1 += sacc[nf][2] + sacc[nf][3];
        }
        rs0 += __shfl_xor_sync(0xffffffffu, rs0, 1);
        rs0 += __shfl_xor_sync(0xffffffffu, rs0, 2);
        rs1 += __shfl_xor_sync(0xffffffffu, rs1, 1);
        rs1 += __shfl_xor_sync(0xffffffffu, rs1, 2);
        l0 = l0 * corr0 + rs0;
        l1 = l1 * corr1 + rs1;
#pragma unroll
        for (int nf = 0; nf < 16; nf++) {
            O[nf][0] *= corr0; O[nf][1] *= corr0;
            O[nf][2] *= corr1; O[nf][3] *= corr1;
        }

        // ---- O += P V ----
#pragma unroll
        for (int kv = 0; kv < 4; kv++) {
            uint32_t ah[4], al[4];
            split2(sacc[2 * kv][0],     sacc[2 * kv][1],     ah[0], al[0]);
            split2(sacc[2 * kv][2],     sacc[2 * kv][3],     ah[1], al[1]);
            split2(sacc[2 * kv + 1][0], sacc[2 * kv + 1][1], ah[2], al[2]);
            split2(sacc[2 * kv + 1][2], sacc[2 * kv + 1][3], ah[3], al[3]);
#pragma unroll
            for (int nf = 0; nf < 16; nf++) {
                uint32_t bb[4];
                LDMX4(bb, base + v_off + nf * 1152 + kv * 32);
                uint32_t bh[2] = {bb[0], bb[1]}, bl[2] = {bb[2], bb[3]};
                MMA4(O[nf], ah, bh);
                MMA4(O[nf], ah, bl);
                MMA4(O[nf], al, bh);
            }
        }
        __syncthreads();
    }

    // ---- write ctx (pre-split hi/lo) ----
    const float inv0 = 1.f / l0, inv1 = 1.f / l1;
    const size_t row0 = bbase + qb + wq * 16 + qr;
#pragma unroll
    for (int nf = 0; nf < 16; nf++) {
        const int col = nf * 8 + qc * 2;
        uint32_t h, l;
        split2(O[nf][0] * inv0, O[nf][1] * inv0, h, l);
        ((uint32_t*)(g_ctxhi + row0 * DH))[col >> 1] = h;
        ((uint32_t*)(g_ctxlo + row0 * DH))[col >> 1] = l;
        split2(O[nf][2] * inv1, O[nf][3] * inv1, h, l);
        ((uint32_t*)(g_ctxhi + (row0 + 8) * DH))[col >> 1] = h;
        ((uint32_t*)(g_ctxlo + (row0 + 8) * DH))[col >> 1] = l;
    }
}

// ---------------------------------------------------------------------------
extern "C" void kernel_launch(void* const* d_in, const int* in_sizes, int n_in,
                              void* d_out, int out_size)
{
    (void)in_sizes; (void)n_in; (void)out_size;
    const float* x  = (const float*)d_in[0];
    const float* wq = (const float*)d_in[1];
    const float* wk = (const float*)d_in[2];
    const float* wv = (const float*)d_in[3];
    const float* wo = (const float*)d_in[4];
    float* out = (float*)d_out;

    cudaFuncSetAttribute(qkv_mma_kernel,
                         cudaFuncAttributeMaxDynamicSharedMemorySize, GEMM_SMEM);
    cudaFuncSetAttribute(out_mma_kernel,
                         cudaFuncAttributeMaxDynamicSharedMemorySize, GEMM_SMEM);
    cudaFuncSetAttribute(attn_mma_kernel,
                         cudaFuncAttributeMaxDynamicSharedMemorySize, ATTN_SMEM);

    prep_x<<<(ROWS * DM) / 1024, 256>>>(x);
    prep_w_qkv<<<dim3(DM, 3), DH>>>(wq, wk, wv);
    prep_wo<<<DH, 256>>>(wo);
    qkv_mma_kernel<<<dim3(ROWS / 64, 3), 256, GEMM_SMEM>>>();
    prep_vt<<<dim3(SEQ / 64, BATCH), 256>>>();
    attn_mma_kernel<<<BATCH * 32, 128, ATTN_SMEM>>>();
    out_mma_kernel<<<dim3(ROWS / 64, DM / 128), 256, GEMM_SMEM>>>(out);
}

// round 12
// speedup vs baseline: 4.6317x; 1.2761x over previous
#include <cuda_runtime.h>
#include <cuda_bf16.h>
#include <cstdint>

#define BATCH 4
#define SEQ 2048
#define DM 1024
#define DH 128
#define ROWS (BATCH * SEQ)   // 8192

// ---------------------------------------------------------------------------
// Scratch (__device__ globals per allocation rules)
// ---------------------------------------------------------------------------
__device__ __align__(16) float g_v[ROWS * DH];      // V f32 (feeds transpose)
__device__ __align__(16) __nv_bfloat16 g_qhi[ROWS * DH];
__device__ __align__(16) __nv_bfloat16 g_qlo[ROWS * DH];
__device__ __align__(16) __nv_bfloat16 g_khi[ROWS * DH];
__device__ __align__(16) __nv_bfloat16 g_klo[ROWS * DH];
__device__ __align__(16) __nv_bfloat16 g_vthi[BATCH * DH * SEQ];  // [b][d][key]
__device__ __align__(16) __nv_bfloat16 g_vtlo[BATCH * DH * SEQ];
__device__ __align__(16) __nv_bfloat16 g_ctxhi[ROWS * DH];
__device__ __align__(16) __nv_bfloat16 g_ctxlo[ROWS * DH];
// split-K attention partials: slot = (b*16 + qt-16)*2 + part
__device__ __align__(16) float g_pO[128][64][DH];
__device__ float g_pm[128][64];
__device__ float g_pl[128][64];
// transposed bf16 hi/lo weights: wT[z][n][k] = w_z[k][n]
__device__ __align__(16) __nv_bfloat16 g_wThi[3 * DH * DM];
__device__ __align__(16) __nv_bfloat16 g_wTlo[3 * DH * DM];
__device__ __align__(16) __nv_bfloat16 g_woThi[DM * DH];
__device__ __align__(16) __nv_bfloat16 g_woTlo[DM * DH];

// ---------------------------------------------------------------------------
// helpers
// ---------------------------------------------------------------------------
__device__ __forceinline__ uint32_t smem_u32(const void* p) {
    uint32_t a;
    asm("{ .reg .u64 t; cvta.to.shared.u64 t, %1; cvt.u32.u64 %0, t; }"
        : "=r"(a) : "l"(p));
    return a;
}
__device__ __forceinline__ uint32_t pack_bf16x2(float x, float y) {
    __nv_bfloat162 t(__float2bfloat16(x), __float2bfloat16(y));  // x -> low
    return *(uint32_t*)&t;
}
__device__ __forceinline__ void split_bf16(float v, __nv_bfloat16& h, float& lo) {
    h = __float2bfloat16(v);
    lo = v - __bfloat162float(h);
}
__device__ __forceinline__ void split2(float x, float y, uint32_t& hi, uint32_t& lo) {
    __nv_bfloat16 hx, hy; float lx, ly;
    split_bf16(x, hx, lx); split_bf16(y, hy, ly);
    __nv_bfloat162 H(hx, hy);
    hi = *(uint32_t*)&H;
    lo = pack_bf16x2(lx, ly);
}

// mma.sync m16n8k16 bf16 -> f32 (HMMA pipe, target-portable)
#define MMA4(c, a, b) asm volatile( \
    "mma.sync.aligned.m16n8k16.row.col.f32.bf16.bf16.f32 " \
    "{%0,%1,%2,%3}, {%4,%5,%6,%7}, {%8,%9}, {%0,%1,%2,%3};" \
    : "+f"((c)[0]), "+f"((c)[1]), "+f"((c)[2]), "+f"((c)[3]) \
    : "r"((a)[0]), "r"((a)[1]), "r"((a)[2]), "r"((a)[3]), \
      "r"((b)[0]), "r"((b)[1]))

#define LDMX4(d, a) asm volatile( \
    "ldmatrix.sync.aligned.m8n8.x4.shared.b16 {%0,%1,%2,%3}, [%4];" \
    : "=r"((d)[0]), "=r"((d)[1]), "=r"((d)[2]), "=r"((d)[3]) : "r"(a))

#define CP_ASYNC16(dst, src) \
    asm volatile("cp.async.cg.shared.global [%0], [%1], 16;" \
                 :: "r"(dst), "l"(src) : "memory")
#define CP_COMMIT asm volatile("cp.async.commit_group;" ::: "memory")
#define CP_WAIT(n) asm volatile("cp.async.wait_group %0;" :: "n"(n) : "memory")

// ---------------------------------------------------------------------------
// Prep kernels
// ---------------------------------------------------------------------------
__global__ void prep_w_qkv(const float* __restrict__ wq,
                           const float* __restrict__ wk,
                           const float* __restrict__ wv) {
    int k = blockIdx.x, z = blockIdx.y, n = threadIdx.x;   // 128 thr
    const float* w = (z == 0) ? wq : (z == 1) ? wk : wv;
    float v = w[k * DH + n];
    __nv_bfloat16 h; float lo; split_bf16(v, h, lo);
    size_t o = (size_t)z * DH * DM + (size_t)n * DM + k;
    g_wThi[o] = h; g_wTlo[o] = __float2bfloat16(lo);
}
__global__ void prep_wo(const float* __restrict__ wo) {
    int k = blockIdx.x;                                    // 128 blocks, 256 thr
#pragma unroll
    for (int i = 0; i < 4; i++) {
        int n = threadIdx.x + i * 256;
        float v = wo[(size_t)k * DM + n];
        __nv_bfloat16 h; float lo; split_bf16(v, h, lo);
        g_woThi[(size_t)n * DH + k] = h;
        g_woTlo[(size_t)n * DH + k] = __float2bfloat16(lo);
    }
}

// V transpose+split: g_v[b*SEQ+key][d] (f32) -> g_vt{hi,lo}[b][d][key] (bf16)
__global__ void prep_vt() {
    __shared__ float ts[64][132];
    const int b = blockIdx.y, k0 = blockIdx.x * 64;
    const int tid = threadIdx.x;
#pragma unroll
    for (int i = 0; i < 8; i++) {
        int id = tid + i * 256;
        int r = id >> 5, c = (id & 31) * 4;
        float4 v = *(const float4*)&g_v[((size_t)b * SEQ + k0 + r) * DH + c];
        ts[r][c] = v.x; ts[r][c + 1] = v.y; ts[r][c + 2] = v.z; ts[r][c + 3] = v.w;
    }
    __syncthreads();
    const int d = tid >> 1, h = tid & 1;
    uint32_t* ohi = (uint32_t*)g_vthi + ((((size_t)b * DH + d) * SEQ + k0) >> 1) + h * 16;
    uint32_t* olo = (uint32_t*)g_vtlo + ((((size_t)b * DH + d) * SEQ + k0) >> 1) + h * 16;
#pragma unroll
    for (int j = 0; j < 16; j++) {
        int key = h * 32 + j * 2;
        uint32_t hv, lv;
        split2(ts[key][d], ts[key + 1][d], hv, lv);
        ohi[j] = hv; olo[j] = lv;
    }
}

// ---------------------------------------------------------------------------
// Generic warp-mma GEMM core, 3-stage cp.async pipeline.
// C[64, 128] = A[64, K] x B[n][k];  BK=32 chunks.
// SPLIT_A: A is f32, staged via 2-slot f32 scratch, split in-kernel.
// else:    A is pre-split bf16 hi/lo, pure cp.async copy.
// 8 warps (2m x 4n); warp tile 32x32; ldmatrix fragment loads.
// bf16 stage: Ahi[64x80B] Alo Bhi[128x80B] Blo = 30720 B, 3 stages.
// f32 scratch: 64 rows x 128 B, 2 slots (SPLIT_A only).
// ---------------------------------------------------------------------------
#define ABY  5120
#define BBY  10240
#define STGB (2 * ABY + 2 * BBY)              // 30720
#define QKV_SMEM (3 * STGB + 2 * 8192)        // 108544
#define OUT_SMEM (3 * STGB)                   // 92160

template <bool SPLIT_A>
__device__ __forceinline__ void gemm_core(
    const float* __restrict__ Af,
    const __nv_bfloat16* __restrict__ Ahi,
    const __nv_bfloat16* __restrict__ Alo, int lda,
    const __nv_bfloat16* __restrict__ Bhig,
    const __nv_bfloat16* __restrict__ Blog, int ldb,
    float* __restrict__ C,
    __nv_bfloat16* __restrict__ Chi, __nv_bfloat16* __restrict__ Clo,
    int ldc, int nc)
{
    extern __shared__ char smg[];
    const uint32_t sbase = smem_u32(smg);
    const int tid  = threadIdx.x;
    const int lane = tid & 31;
    const int wid  = tid >> 5;
    const int warpM = wid >> 2;
    const int warpN = wid & 3;
    const int qr = lane >> 2, qc = lane & 3;

    float acc[2][4][4];
#pragma unroll
    for (int mt = 0; mt < 2; mt++)
#pragma unroll
        for (int nt = 0; nt < 4; nt++)
#pragma unroll
            for (int i = 0; i < 4; i++) acc[mt][nt][i] = 0.f;

    auto issue = [&](int c) {
        // B: 1024 x 16B
        const uint32_t bstg = sbase + (c % 3) * STGB + 2 * ABY;
#pragma unroll
        for (int i = 0; i < 4; i++) {
            int u = tid + i * 256;
            int r = u >> 3, cc = u & 3, hf = (u >> 2) & 1;
            CP_ASYNC16(bstg + (hf ? BBY : 0) + r * 80 + cc * 16,
                       (const char*)((hf ? Blog : Bhig) +
                                     (size_t)r * ldb + c * 32 + cc * 8));
        }
        if (SPLIT_A) {
            // X f32: 512 x 16B into f32 slot c&1
            const uint32_t fstg = sbase + 3 * STGB + (c & 1) * 8192;
#pragma unroll
            for (int i = 0; i < 2; i++) {
                int u = tid + i * 256;
                int r = u >> 3, j = u & 7;
                CP_ASYNC16(fstg + r * 128 + j * 16,
                           (const char*)(Af + (size_t)r * lda + c * 32 + j * 4));
            }
        } else {
            // A: 512 x 16B pure copy
            const uint32_t astg = sbase + (c % 3) * STGB;
#pragma unroll
            for (int i = 0; i < 2; i++) {
                int u = tid + i * 256;
                int r = u >> 3, cc = u & 3, hf = (u >> 2) & 1;
                CP_ASYNC16(astg + (hf ? ABY : 0) + r * 80 + cc * 16,
                           (const char*)((hf ? Alo : Ahi) +
                                         (size_t)r * lda + c * 32 + cc * 8));
            }
        }
    };

    issue(0); CP_COMMIT;
    if (nc > 1) { issue(1); CP_COMMIT; }

    const uint32_t aoff_hi = (warpM * 32 + (lane & 15)) * 80 + ((lane >> 4) & 1) * 16;
    const uint32_t aoff_lo = aoff_hi + ABY;
    const uint32_t boff = 2 * ABY + ((lane & 16) ? BBY : 0) +
                          (warpN * 32 + (lane & 7)) * 80 + ((lane >> 3) & 1) * 16;

    for (int c = 0; c < nc; c++) {
        if (c + 1 < nc) CP_WAIT(1); else CP_WAIT(0);
        __syncthreads();

        const uint32_t bufb = sbase + (c % 3) * STGB;
        if (SPLIT_A) {
            // split f32 slot -> bf16 hi/lo stage
            const uint32_t fstg = sbase + 3 * STGB + (c & 1) * 8192;
#pragma unroll
            for (int i = 0; i < 2; i++) {
                int u = tid + i * 256;
                int r = u >> 3, j = u & 7;
                float vx, vy, vz, vw;
                asm volatile("ld.shared.v4.f32 {%0,%1,%2,%3}, [%4];"
                             : "=f"(vx), "=f"(vy), "=f"(vz), "=f"(vw)
                             : "r"(fstg + r * 128 + j * 16));
                uint32_t h0, l0, h1, l1;
                split2(vx, vy, h0, l0);
                split2(vz, vw, h1, l1);
                asm volatile("st.shared.v2.b32 [%0], {%1,%2};"
                             :: "r"(bufb + r * 80 + j * 8), "r"(h0), "r"(h1) : "memory");
                asm volatile("st.shared.v2.b32 [%0], {%1,%2};"
                             :: "r"(bufb + ABY + r * 80 + j * 8), "r"(l0), "r"(l1) : "memory");
            }
            __syncthreads();
        }
        if (c + 2 < nc) { issue(c + 2); CP_COMMIT; }

#pragma unroll
        for (int s = 0; s < 2; s++) {
            uint32_t ah[2][4], al[2][4];
#pragma unroll
            for (int mt = 0; mt < 2; mt++) {
                LDMX4(ah[mt], bufb + aoff_hi + mt * 16 * 80 + s * 32);
                LDMX4(al[mt], bufb + aoff_lo + mt * 16 * 80 + s * 32);
            }
#pragma unroll
            for (int nt = 0; nt < 4; nt++) {
                uint32_t bb[4];
                LDMX4(bb, bufb + boff + nt * 8 * 80 + s * 32);
                uint32_t bh[2] = {bb[0], bb[1]}, bl[2] = {bb[2], bb[3]};
#pragma unroll
                for (int mt = 0; mt < 2; mt++) {
                    MMA4(acc[mt][nt], ah[mt], bh);
                    MMA4(acc[mt][nt], ah[mt], bl);
                    MMA4(acc[mt][nt], al[mt], bh);
                }
            }
        }
    }

#pragma unroll
    for (int mt = 0; mt < 2; mt++)
#pragma unroll
        for (int nt = 0; nt < 4; nt++) {
            int r = warpM * 32 + mt * 16 + qr;
            int col = warpN * 32 + nt * 8 + qc * 2;
            if (Chi) {
                uint32_t h0, l0, h1, l1;
                split2(acc[mt][nt][0], acc[mt][nt][1], h0, l0);
                split2(acc[mt][nt][2], acc[mt][nt][3], h1, l1);
                ((uint32_t*)(Chi + (size_t)r * ldc))[col >> 1] = h0;
                ((uint32_t*)(Clo + (size_t)r * ldc))[col >> 1] = l0;
                ((uint32_t*)(Chi + (size_t)(r + 8) * ldc))[col >> 1] = h1;
                ((uint32_t*)(Clo + (size_t)(r + 8) * ldc))[col >> 1] = l1;
            } else {
                *(float2*)(C + (size_t)r * ldc + col) =
                    make_float2(acc[mt][nt][0], acc[mt][nt][1]);
                *(float2*)(C + (size_t)(r + 8) * ldc + col) =
                    make_float2(acc[mt][nt][2], acc[mt][nt][3]);
            }
        }
}

// qkv: grid (128, 3): 64 rows/CTA, K=1024 (nc=32), N=128. A = raw f32 x.
__global__ __launch_bounds__(256, 2) void qkv_mma_kernel(const float* __restrict__ x) {
    const int z = blockIdx.y, bx = blockIdx.x;
    const __nv_bfloat16* Bh = g_wThi + (size_t)z * DH * DM;
    const __nv_bfloat16* Bl = g_wTlo + (size_t)z * DH * DM;
    const size_t rb = (size_t)bx * 64;
    float* C = nullptr; __nv_bfloat16 *Chi = nullptr, *Clo = nullptr;
    if (z == 0)      { Chi = g_qhi + rb * DH; Clo = g_qlo + rb * DH; }
    else if (z == 1) { Chi = g_khi + rb * DH; Clo = g_klo + rb * DH; }
    else             { C = g_v + rb * DH; }
    gemm_core<true>(x + rb * DM, nullptr, nullptr, DM, Bh, Bl, DM, C, Chi, Clo, DH, 32);
}

// out: grid (128, 8): 64 rows, n-slab 128, K=128 (nc=4). A = ctx hi/lo.
__global__ __launch_bounds__(256, 2) void out_mma_kernel(float* __restrict__ out) {
    const int bx = blockIdx.x, by = blockIdx.y;
    const __nv_bfloat16* Bh = g_woThi + (size_t)by * 128 * DH;
    const __nv_bfloat16* Bl = g_woTlo + (size_t)by * 128 * DH;
    float* C = out + (size_t)bx * 64 * DM + by * 128;
    gemm_core<false>(nullptr, g_ctxhi + (size_t)bx * 64 * DH,
                     g_ctxlo + (size_t)bx * 64 * DH, DH,
                     Bh, Bl, DH, C, nullptr, nullptr, DM, 4);
}

// ---------------------------------------------------------------------------
// Tensor-core causal flash attention with split-K balance.
// BQ=64, BK=64, 4 warps. Work items (grid=192, longest-first):
//   bid   0..63 : qt>=16 part 0 (kt 0..15)        -> partial
//   bid  64..127: qt>=16 part 1 (kt 16..qt)       -> partial (desc length)
//   bid 128..191: qt<16 single (kt 0..qt)         -> direct ctx (desc length)
// ---------------------------------------------------------------------------
#define ATTN_SMEM 178176

__device__ __forceinline__ void attn_issue_tile(
    uint32_t sbase, int tid, int b, int kt, int p, size_t bbase)
{
    const uint32_t base = sbase + 34816 + p * 71680;
    const int k0 = kt * 64;
    const char* khi_g = (const char*)(g_khi + (bbase + k0) * DH);
    const char* klo_g = (const char*)(g_klo + (bbase + k0) * DH);
    const char* vhi_g = (const char*)g_vthi + (((size_t)b * DH) * SEQ + k0) * 2;
    const char* vlo_g = (const char*)g_vtlo + (((size_t)b * DH) * SEQ + k0) * 2;
#pragma unroll
    for (int i = 0; i < 8; i++) {
        int id = tid + i * 128;
        int r  = id >> 4, off  = (id & 15) * 16;   // K: 64 rows x 256B
        CP_ASYNC16(base + r * 272 + off, khi_g + (size_t)r * 256 + off);
        CP_ASYNC16(base + 17408 + r * 272 + off, klo_g + (size_t)r * 256 + off);
        int rv = id >> 3, offv = (id & 7) * 16;    // Vt: 128 rows x 128B
        CP_ASYNC16(base + 34816 + rv * 144 + offv,
                   vhi_g + (size_t)rv * (SEQ * 2) + offv);
        CP_ASYNC16(base + 53248 + rv * 144 + offv,
                   vlo_g + (size_t)rv * (SEQ * 2) + offv);
    }
}

__global__ __launch_bounds__(128, 1) void attn_mma_kernel()
{
    extern __shared__ char sm[];
    const uint32_t sbase = smem_u32(sm);
    const int tid  = threadIdx.x;
    const int lane = tid & 31;
    const int wq   = tid >> 5;
    const int qr   = lane >> 2, qc = lane & 3;

    // ---- work-item mapping ----
    const int bid = blockIdx.x;
    int b, qt, kt0, kt1, part;
    bool partial;
    if (bid < 64) {
        b = bid & 3; qt = 16 + (bid >> 2); kt0 = 0; kt1 = 15;
        partial = true; part = 0;
    } else if (bid < 128) {
        int i = bid - 64;
        b = i & 3; qt = 31 - (i >> 2); kt0 = 16; kt1 = qt;
        partial = true; part = 1;
    } else {
        int i = bid - 128;
        b = i & 3; qt = 15 - (i >> 2); kt0 = 0; kt1 = qt;
        partial = false; part = 0;
    }
    const int qb = qt * 64;
    const size_t bbase = (size_t)b * SEQ;
    const int ntiles = kt1 - kt0 + 1;
    const float scale = 0.08838834764831845f;

    {
        const char* qhi_g = (const char*)(g_qhi + (bbase + qb) * DH);
        const char* qlo_g = (const char*)(g_qlo + (bbase + qb) * DH);
#pragma unroll
        for (int i = 0; i < 8; i++) {
            int id = tid + i * 128;
            int r = id >> 4, off = (id & 15) * 16;
            CP_ASYNC16(sbase + r * 272 + off, qhi_g + (size_t)r * 256 + off);
            CP_ASYNC16(sbase + 17408 + r * 272 + off, qlo_g + (size_t)r * 256 + off);
        }
        attn_issue_tile(sbase, tid, b, kt0, 0, bbase);
        CP_COMMIT;
    }

    const uint32_t q_hi_addr = sbase + (wq * 16 + (lane & 15)) * 272 +
                               ((lane >> 4) & 1) * 16;
    const uint32_t q_lo_addr = q_hi_addr + 17408;
    const uint32_t k_off = ((lane & 16) ? 17408u : 0u) +
                           (lane & 7) * 272 + ((lane >> 3) & 1) * 16;
    const uint32_t v_off = 34816u + ((lane & 16) ? 18432u : 0u) +
                           (lane & 7) * 144 + ((lane >> 3) & 1) * 16;

    float O[16][4];
#pragma unroll
    for (int nf = 0; nf < 16; nf++)
#pragma unroll
        for (int i = 0; i < 4; i++) O[nf][i] = 0.f;
    float m0 = -1e30f, m1 = -1e30f, l0 = 0.f, l1 = 0.f;

    for (int t = 0; t < ntiles; t++) {
        const int kt = kt0 + t;
        const int p = t & 1;
        if (t + 1 < ntiles) {
            attn_issue_tile(sbase, tid, b, kt + 1, p ^ 1, bbase);
            CP_COMMIT;
            CP_WAIT(1);
        } else {
            CP_WAIT(0);
        }
        __syncthreads();

        const uint32_t base = sbase + 34816 + p * 71680;

        // ---- S = Q K^T ----
        float sacc[8][4];
#pragma unroll
        for (int nf = 0; nf < 8; nf++)
#pragma unroll
            for (int i = 0; i < 4; i++) sacc[nf][i] = 0.f;

#pragma unroll
        for (int kf = 0; kf < 8; kf++) {
            uint32_t ah[4], al[4];
            LDMX4(ah, q_hi_addr + kf * 32);
            LDMX4(al, q_lo_addr + kf * 32);
#pragma unroll
            for (int nf = 0; nf < 8; nf++) {
                uint32_t bb[4];
                LDMX4(bb, base + k_off + nf * 2176 + kf * 32);
                uint32_t bh[2] = {bb[0], bb[1]}, bl[2] = {bb[2], bb[3]};
                MMA4(sacc[nf], ah, bh);
                MMA4(sacc[nf], ah, bl);
                MMA4(sacc[nf], al, bh);
            }
        }

        // ---- scale + causal mask ----
#pragma unroll
        for (int nf = 0; nf < 8; nf++)
#pragma unroll
            for (int i = 0; i < 4; i++) sacc[nf][i] *= scale;
        if (kt == qt) {
            const int q0 = wq * 16 + qr, q1 = q0 + 8;
#pragma unroll
            for (int nf = 0; nf < 8; nf++) {
                const int key = nf * 8 + qc * 2;
                if (key > q0)     sacc[nf][0] = -1e30f;
                if (key + 1 > q0) sacc[nf][1] = -1e30f;
                if (key > q1)     sacc[nf][2] = -1e30f;
                if (key + 1 > q1) sacc[nf][3] = -1e30f;
            }
        }

        // ---- online softmax ----
        float mt0 = -1e30f, mt1 = -1e30f;
#pragma unroll
        for (int nf = 0; nf < 8; nf++) {
            mt0 = fmaxf(mt0, fmaxf(sacc[nf][0], sacc[nf][1]));
            mt1 = fmaxf(mt1, fmaxf(sacc[nf][2], sacc[nf][3]));
        }
        mt0 = fmaxf(mt0, __shfl_xor_sync(0xffffffffu, mt0, 1));
        mt0 = fmaxf(mt0, __shfl_xor_sync(0xffffffffu, mt0, 2));
        mt1 = fmaxf(mt1, __shfl_xor_sync(0xffffffffu, mt1, 1));
        mt1 = fmaxf(mt1, __shfl_xor_sync(0xffffffffu, mt1, 2));
        const float nm0 = fmaxf(m0, mt0), nm1 = fmaxf(m1, mt1);
        const float corr0 = __expf(m0 - nm0), corr1 = __expf(m1 - nm1);
        m0 = nm0; m1 = nm1;

        float rs0 = 0.f, rs1 = 0.f;
#pragma unroll
        for (int nf = 0; nf < 8; nf++) {
            sacc[nf][0] = __expf(sacc[nf][0] - nm0);
            sacc[nf][1] = __expf(sacc[nf][1] - nm0);
            sacc[nf][2] = __expf(sacc[nf][2] - nm1);
            sacc[nf][3] = __expf(sacc[nf][3] - nm1);
            rs0 += sacc[nf][0] + sacc[nf][1];
            rs1 += sacc[nf][2] + sacc[nf][3];
        }
        rs0 += __shfl_xor_sync(0xffffffffu, rs0, 1);
        rs0 += __shfl_xor_sync(0xffffffffu, rs0, 2);
        rs1 += __shfl_xor_sync(0xffffffffu, rs1, 1);
        rs1 += __shfl_xor_sync(0xffffffffu, rs1, 2);
        l0 = l0 * corr0 + rs0;
        l1 = l1 * corr1 + rs1;
#pragma unroll
        for (int nf = 0; nf < 16; nf++) {
            O[nf][0] *= corr0; O[nf][1] *= corr0;
            O[nf][2] *= corr1; O[nf][3] *= corr1;
        }

        // ---- O += P V ----
#pragma unroll
        for (int kv = 0; kv < 4; kv++) {
            uint32_t ah[4], al[4];
            split2(sacc[2 * kv][0],     sacc[2 * kv][1],     ah[0], al[0]);
            split2(sacc[2 * kv][2],     sacc[2 * kv][3],     ah[1], al[1]);
            split2(sacc[2 * kv + 1][0], sacc[2 * kv + 1][1], ah[2], al[2]);
            split2(sacc[2 * kv + 1][2], sacc[2 * kv + 1][3], ah[3], al[3]);
#pragma unroll
            for (int nf = 0; nf < 16; nf++) {
                uint32_t bb[4];
                LDMX4(bb, base + v_off + nf * 1152 + kv * 32);
                uint32_t bh[2] = {bb[0], bb[1]}, bl[2] = {bb[2], bb[3]};
                MMA4(O[nf], ah, bh);
                MMA4(O[nf], ah, bl);
                MMA4(O[nf], al, bh);
            }
        }
        __syncthreads();
    }

    if (partial) {
        // ---- store raw partial (m, l, O) ----
        const int slot = ((b * 16 + (qt - 16)) << 1) + part;
        const int lr0 = wq * 16 + qr, lr1 = lr0 + 8;
        if (qc == 0) {
            g_pm[slot][lr0] = m0; g_pl[slot][lr0] = l0;
            g_pm[slot][lr1] = m1; g_pl[slot][lr1] = l1;
        }
#pragma unroll
        for (int nf = 0; nf < 16; nf++) {
            const int col = nf * 8 + qc * 2;
            *(float2*)&g_pO[slot][lr0][col] = make_float2(O[nf][0], O[nf][1]);
            *(float2*)&g_pO[slot][lr1][col] = make_float2(O[nf][2], O[nf][3]);
        }
    } else {
        // ---- direct: normalize + split-store ctx ----
        const float inv0 = 1.f / l0, inv1 = 1.f / l1;
        const size_t row0 = bbase + qb + wq * 16 + qr;
#pragma unroll
        for (int nf = 0; nf < 16; nf++) {
            const int col = nf * 8 + qc * 2;
            uint32_t h, l;
            split2(O[nf][0] * inv0, O[nf][1] * inv0, h, l);
            ((uint32_t*)(g_ctxhi + row0 * DH))[col >> 1] = h;
            ((uint32_t*)(g_ctxlo + row0 * DH))[col >> 1] = l;
            split2(O[nf][2] * inv1, O[nf][3] * inv1, h, l);
            ((uint32_t*)(g_ctxhi + (row0 + 8) * DH))[col >> 1] = h;
            ((uint32_t*)(g_ctxlo + (row0 + 8) * DH))[col >> 1] = l;
        }
    }
}

// combine partials for qt>=16: grid (16, 4), 256 threads.
__global__ void attn_combine() {
    const int qt = 16 + blockIdx.x, b = blockIdx.y;
    const int slotA = ((b * 16 + blockIdx.x) << 1), slotB = slotA + 1;
    const int tid = threadIdx.x;
    const int r = tid >> 2, seg = (tid & 3) * 32;
    const float mA = g_pm[slotA][r], mB = g_pm[slotB][r];
    const float m = fmaxf(mA, mB);
    float wA = __expf(mA - m), wB = __expf(mB - m);
    const float inv = 1.f / (g_pl[slotA][r] * wA + g_pl[slotB][r] * wB);
    wA *= inv; wB *= inv;
    const size_t grow = (size_t)b * SEQ + (size_t)qt * 64 + r;
#pragma unroll
    for (int c = 0; c < 32; c += 2) {
        const int col = seg + c;
        float2 a = *(float2*)&g_pO[slotA][r][col];
        float2 bv = *(float2*)&g_pO[slotB][r][col];
        uint32_t h, l;
        split2(a.x * wA + bv.x * wB, a.y * wA + bv.y * wB, h, l);
        ((uint32_t*)(g_ctxhi + grow * DH))[col >> 1] = h;
        ((uint32_t*)(g_ctxlo + grow * DH))[col >> 1] = l;
    }
}

// ---------------------------------------------------------------------------
extern "C" void kernel_launch(void* const* d_in, const int* in_sizes, int n_in,
                              void* d_out, int out_size)
{
    (void)in_sizes; (void)n_in; (void)out_size;
    const float* x  = (const float*)d_in[0];
    const float* wq = (const float*)d_in[1];
    const float* wk = (const float*)d_in[2];
    const float* wv = (const float*)d_in[3];
    const float* wo = (const float*)d_in[4];
    float* out = (float*)d_out;

    cudaFuncSetAttribute(qkv_mma_kernel,
                         cudaFuncAttributeMaxDynamicSharedMemorySize, QKV_SMEM);
    cudaFuncSetAttribute(out_mma_kernel,
                         cudaFuncAttributeMaxDynamicSharedMemorySize, OUT_SMEM);
    cudaFuncSetAttribute(attn_mma_kernel,
                         cudaFuncAttributeMaxDynamicSharedMemorySize, ATTN_SMEM);

    prep_w_qkv<<<dim3(DM, 3), DH>>>(wq, wk, wv);
    prep_wo<<<DH, 256>>>(wo);
    qkv_mma_kernel<<<dim3(ROWS / 64, 3), 256, QKV_SMEM>>>(x);
    prep_vt<<<dim3(SEQ / 64, BATCH), 256>>>();
    attn_mma_kernel<<<192, 128, ATTN_SMEM>>>();
    attn_combine<<<dim3(16, BATCH), 256>>>();
    out_mma_kernel<<<dim3(ROWS / 64, DM / 128), 256, OUT_SMEM>>>(out);
}